// round 1
// baseline (speedup 1.0000x reference)
#include <cuda_runtime.h>
#include <cstdint>

// Problem constants (fixed shapes per reference)
#define T_TOK 8192
#define DDIM  1024
#define HDIM  1024
#define DOUT  1024
#define NEXP  8
#define TOPK  2
#define NSLOT (T_TOK*TOPK)   // 16384
#define CAP   NSLOT

// Scratch (device globals: allowed; no runtime allocation)
__device__ float g_h[(size_t)NSLOT * HDIM];     // 64 MB: stage-1 outputs per slot
__device__ float g_o[(size_t)NSLOT * DOUT];     // 64 MB: stage-2 outputs per slot (gate-scaled)
__device__ float g_gates[NSLOT];
__device__ int   g_lists[NEXP * CAP];
__device__ int   g_counts[NEXP];

// ---------------------------------------------------------------------------
__global__ void zero_counts_kernel() {
    if (threadIdx.x < NEXP) g_counts[threadIdx.x] = 0;
}

// ---------------------------------------------------------------------------
// Router: one warp per token. logits = x[t] @ Wr, softmax, top-2 (lower index
// wins ties, matching jax.lax.top_k), append slot ids to per-expert lists.
__global__ void router_kernel(const float* __restrict__ x,
                              const float* __restrict__ Wr) {
    __shared__ float sWr[NEXP][DDIM];   // transposed for conflict-free reads
    int tid = threadIdx.x;
    for (int i = tid; i < DDIM * NEXP; i += blockDim.x) {
        int d = i >> 3, e = i & 7;      // Wr row-major [D][E]
        sWr[e][d] = Wr[i];
    }
    __syncthreads();

    int warp = tid >> 5, lane = tid & 31;
    int token = blockIdx.x * 8 + warp;
    if (token >= T_TOK) return;
    const float* xr = x + (size_t)token * DDIM;

    float acc[NEXP];
#pragma unroll
    for (int e = 0; e < NEXP; e++) acc[e] = 0.f;
    for (int i = lane; i < DDIM; i += 32) {
        float xv = xr[i];
#pragma unroll
        for (int e = 0; e < NEXP; e++) acc[e] += xv * sWr[e][i];
    }
#pragma unroll
    for (int e = 0; e < NEXP; e++) {
#pragma unroll
        for (int off = 16; off > 0; off >>= 1)
            acc[e] += __shfl_xor_sync(0xffffffffu, acc[e], off);
    }
    if (lane == 0) {
        float mx = acc[0];
#pragma unroll
        for (int e = 1; e < NEXP; e++) mx = fmaxf(mx, acc[e]);
        float p[NEXP], s = 0.f;
#pragma unroll
        for (int e = 0; e < NEXP; e++) { p[e] = expf(acc[e] - mx); s += p[e]; }
        float inv = 1.f / s;
#pragma unroll
        for (int e = 0; e < NEXP; e++) p[e] *= inv;

        // top-1 (strict >, ascending scan => lowest index on tie)
        int i0 = 0; float b0 = p[0];
#pragma unroll
        for (int e = 1; e < NEXP; e++) if (p[e] > b0) { b0 = p[e]; i0 = e; }
        // top-2
        int i1 = -1; float b1 = -1.f;
#pragma unroll
        for (int e = 0; e < NEXP; e++)
            if (e != i0 && p[e] > b1) { b1 = p[e]; i1 = e; }

        int s0 = token * 2, s1 = token * 2 + 1;
        g_gates[s0] = b0;
        g_gates[s1] = b1;
        int pos0 = atomicAdd(&g_counts[i0], 1);
        g_lists[i0 * CAP + pos0] = s0;
        int pos1 = atomicAdd(&g_counts[i1], 1);
        g_lists[i1 * CAP + pos1] = s1;
    }
}

// ---------------------------------------------------------------------------
// Grouped GEMM with gathered A rows, tf32 mma.sync (m16n8k8).
// STAGE 1: A = x[slot>>1], B = Wi[e], C = g_h[slot]
// STAGE 2: A = g_h[slot],  B = Wo[e], C = g_o[slot] * gate[slot]
#define BM 128
#define BN 128
#define BK 32
#define LDA 36     // pad: conflict-free frag loads
#define LDB 136

__device__ __forceinline__ unsigned f2tf32(float f) {
    unsigned r;
    asm("cvt.rna.tf32.f32 %0, %1;" : "=r"(r) : "f"(f));
    return r;
}

__device__ __forceinline__ void mma_tf32(float* c, const unsigned* a, const unsigned* b) {
    asm volatile(
        "mma.sync.aligned.m16n8k8.row.col.f32.tf32.tf32.f32 "
        "{%0,%1,%2,%3}, {%4,%5,%6,%7}, {%8,%9}, {%0,%1,%2,%3};\n"
        : "+f"(c[0]), "+f"(c[1]), "+f"(c[2]), "+f"(c[3])
        : "r"(a[0]), "r"(a[1]), "r"(a[2]), "r"(a[3]), "r"(b[0]), "r"(b[1]));
}

template <int STAGE>
__global__ __launch_bounds__(256)
void moe_gemm_kernel(const float* __restrict__ x, const float* __restrict__ Wbase) {
    const int e = blockIdx.z;
    const int cnt = g_counts[e];
    const int m0 = blockIdx.y * BM;
    if (m0 >= cnt) return;
    const int n0 = blockIdx.x * BN;

    const float* Asrc = (STAGE == 1) ? x : g_h;
    float*       Cdst = (STAGE == 1) ? g_h : g_o;
    const float* B = Wbase + (size_t)e * DDIM * HDIM;  // [K][N] row-major
    const int* lst = g_lists + e * CAP + m0;

    __shared__ float sA[BM * LDA];
    __shared__ float sB[BK * LDB];

    const int tid = threadIdx.x;

    // A loader: 4 rows, r = (tid>>3) + 32p, 16B per row per thread
    const int acol = (tid & 7) * 4;
    const int arow = tid >> 3;
    const float* aptr[4];
#pragma unroll
    for (int p = 0; p < 4; p++) {
        int r = arow + 32 * p;
        if (m0 + r < cnt) {
            int slot = lst[r];
            size_t row = (STAGE == 1) ? (size_t)(slot >> 1) : (size_t)slot;
            aptr[p] = Asrc + row * 1024 + acol;
        } else {
            aptr[p] = nullptr;
        }
    }
    // B loader: k = (tid>>5) + 8p, 16B per row per thread
    const int bk0 = tid >> 5;
    const int bcol = (tid & 31) * 4;
    const float* bptr = B + (size_t)bk0 * 1024 + n0 + bcol;

    const int warp = tid >> 5, lane = tid & 31;
    const int wm = warp & 1, wn = warp >> 1;   // warp tile 64x32
    const int g = lane >> 2, tg = lane & 3;

    float c[4][4][4];
#pragma unroll
    for (int i = 0; i < 4; i++)
#pragma unroll
        for (int j = 0; j < 4; j++)
#pragma unroll
            for (int q = 0; q < 4; q++) c[i][j][q] = 0.f;

    float4 aReg[4], bReg[4];
#pragma unroll
    for (int p = 0; p < 4; p++)
        aReg[p] = aptr[p] ? *(const float4*)(aptr[p]) : make_float4(0.f, 0.f, 0.f, 0.f);
#pragma unroll
    for (int p = 0; p < 4; p++)
        bReg[p] = *(const float4*)(bptr + (size_t)(8 * p) * 1024);

    for (int kt = 0; kt < 32; kt++) {
        if (kt) __syncthreads();   // previous compute done before overwrite
        // cvt.rna to tf32 during smem store: inner loop stays pure LDS+MMA
#pragma unroll
        for (int p = 0; p < 4; p++) {
            int r = arow + 32 * p;
            float* d = &sA[r * LDA + acol];
            float4 v = aReg[p];
            d[0] = __uint_as_float(f2tf32(v.x));
            d[1] = __uint_as_float(f2tf32(v.y));
            d[2] = __uint_as_float(f2tf32(v.z));
            d[3] = __uint_as_float(f2tf32(v.w));
        }
#pragma unroll
        for (int p = 0; p < 4; p++) {
            int k = bk0 + 8 * p;
            float* d = &sB[k * LDB + bcol];
            float4 v = bReg[p];
            d[0] = __uint_as_float(f2tf32(v.x));
            d[1] = __uint_as_float(f2tf32(v.y));
            d[2] = __uint_as_float(f2tf32(v.z));
            d[3] = __uint_as_float(f2tf32(v.w));
        }
        __syncthreads();

        if (kt < 31) {   // prefetch next tile into registers, overlaps compute
            int koff = (kt + 1) * BK;
#pragma unroll
            for (int p = 0; p < 4; p++)
                aReg[p] = aptr[p] ? *(const float4*)(aptr[p] + koff)
                                  : make_float4(0.f, 0.f, 0.f, 0.f);
#pragma unroll
            for (int p = 0; p < 4; p++)
                bReg[p] = *(const float4*)(bptr + (size_t)(koff + 8 * p) * 1024);
        }

#pragma unroll
        for (int ks = 0; ks < 4; ks++) {
            unsigned a[4][4], b[4][2];
#pragma unroll
            for (int mf = 0; mf < 4; mf++) {
                int row = wm * 64 + mf * 16 + g;
                int col = ks * 8 + tg;
                a[mf][0] = __float_as_uint(sA[row * LDA + col]);
                a[mf][1] = __float_as_uint(sA[(row + 8) * LDA + col]);
                a[mf][2] = __float_as_uint(sA[row * LDA + col + 4]);
                a[mf][3] = __float_as_uint(sA[(row + 8) * LDA + col + 4]);
            }
#pragma unroll
            for (int nf = 0; nf < 4; nf++) {
                int coln = wn * 32 + nf * 8 + g;
                int krow = ks * 8 + tg;
                b[nf][0] = __float_as_uint(sB[krow * LDB + coln]);
                b[nf][1] = __float_as_uint(sB[(krow + 4) * LDB + coln]);
            }
#pragma unroll
            for (int mf = 0; mf < 4; mf++)
#pragma unroll
                for (int nf = 0; nf < 4; nf++)
                    mma_tf32(c[mf][nf], a[mf], b[nf]);
        }
    }

    // Epilogue: scatter to C rows (slots); stage 2 scales by gate
#pragma unroll
    for (int mf = 0; mf < 4; mf++) {
#pragma unroll
        for (int half = 0; half < 2; half++) {
            int r = wm * 64 + mf * 16 + g + half * 8;
            if (m0 + r >= cnt) continue;
            int slot = lst[r];
            float gate = (STAGE == 2) ? g_gates[slot] : 1.0f;
            float* crow = Cdst + (size_t)slot * 1024 + n0;
#pragma unroll
            for (int nf = 0; nf < 4; nf++) {
                int cc = wn * 32 + nf * 8 + tg * 2;
                float2 v;
                v.x = c[mf][nf][half * 2 + 0] * gate;
                v.y = c[mf][nf][half * 2 + 1] * gate;
                *(float2*)(crow + cc) = v;
            }
        }
    }
}

// ---------------------------------------------------------------------------
// out[t] = o[2t] + o[2t+1]  (gate already applied in stage-2 epilogue)
__global__ void combine_kernel(float* __restrict__ out) {
    size_t i = (size_t)blockIdx.x * blockDim.x + threadIdx.x;  // float4 index
    size_t t = i >> 8;           // DOUT/4 = 256 float4 per row
    size_t cc = i & 255;
    const float4* o4 = (const float4*)g_o;
    float4 a = o4[(t * 2) * 256 + cc];
    float4 b = o4[(t * 2 + 1) * 256 + cc];
    float4 r;
    r.x = a.x + b.x; r.y = a.y + b.y; r.z = a.z + b.z; r.w = a.w + b.w;
    ((float4*)out)[i] = r;
}

// ---------------------------------------------------------------------------
extern "C" void kernel_launch(void* const* d_in, const int* in_sizes, int n_in,
                              void* d_out, int out_size) {
    const float* x  = (const float*)d_in[0];   // [B,S,D] = [T,1024]
    const float* Wr = (const float*)d_in[1];   // [1024,8]
    const float* Wi = (const float*)d_in[2];   // [8,1024,1024]
    const float* Wo = (const float*)d_in[3];   // [8,1024,1024]
    float* out = (float*)d_out;                // [T,1024]
    (void)in_sizes; (void)n_in; (void)out_size;

    zero_counts_kernel<<<1, 32>>>();
    router_kernel<<<T_TOK / 8, 256>>>(x, Wr);

    dim3 ggrid(BN == 128 ? 8 : 16, CAP / BM, NEXP);  // (Ntiles, Mtiles, experts)
    moe_gemm_kernel<1><<<ggrid, 256>>>(x, Wi);
    moe_gemm_kernel<2><<<ggrid, 256>>>(x, Wo);

    combine_kernel<<<(T_TOK * DOUT / 4) / 256, 256>>>(out);
}

// round 3
// speedup vs baseline: 1.8780x; 1.8780x over previous
#include <cuda_runtime.h>
#include <cuda.h>
#include <cuda_fp16.h>
#include <cstdint>

// ===========================================================================
// Feature gate: tcgen05 only exists in the 'a' (arch-specific) device pass.
#if defined(__CUDA_ARCH_FEAT_SM100_ALL) || defined(__CUDA_ARCH_FEAT_SM103_ALL)
#define HAS_TC 1
#else
#define HAS_TC 0
#endif

// Problem constants
#define T_TOK 8192
#define NEXP  8
#define NSLOT (T_TOK*2)
#define CAP   NSLOT

// tcgen05 GEMM tiling (fp16): chunk = 64 halves = 128B row
#define NST   4
#define KC    64
#define NCHUNK 16
#define TM    128
#define TN    256
#define A_TILE_B (TM*128)    // 16 KB
#define B_TILE_B (TN*128)    // 32 KB
#define SM_TMEM  0
#define SM_FULL  64
#define SM_EMPTY 128
#define SM_DONE  192
#define SM_A     1024
#define SM_B     (SM_A + NST*A_TILE_B)
#define SMEM_TOTAL (SM_B + NST*B_TILE_B)   // 197632

// tcgen05 idesc, kind::f16: cfmt F32=1<<4, atype/btype F16=0, N/8<<17, M/16<<24
#define IDESC ((1u<<4)|((unsigned)(TN/8)<<17)|((unsigned)(TM/16)<<24))

// ===========================================================================
// Device scratch
__device__ float  g_h[(size_t)NSLOT * 1024];
__device__ float  g_o[(size_t)NSLOT * 1024];
__device__ __half g_wt16[(size_t)16 * 1024 * 1024];   // [mat*8+e][n][k] fp16
__device__ float  g_gates[NSLOT];
__device__ int    g_lists[NEXP * CAP];
__device__ int    g_counts[NEXP];
__device__ int    g_tc_done;
__device__ __align__(128) CUtensorMap g_tmap;

// ===========================================================================
// Helpers
__device__ __forceinline__ uint32_t smem_u32(const void* p) {
    uint32_t a;
    asm("{ .reg .u64 t; cvta.to.shared.u64 t, %1; cvt.u32.u64 %0, t; }" : "=r"(a) : "l"(p));
    return a;
}
__device__ __forceinline__ uint32_t elect_one_pred() {
    uint32_t p;
    asm volatile("{\n\t.reg .pred p;\n\telect.sync _|p, 0xFFFFFFFF;\n\t"
                 "selp.b32 %0, 1, 0, p;\n\t}" : "=r"(p));
    return p;
}
#define MBARRIER_INIT(addr, cnt) \
    asm volatile("mbarrier.init.shared.b64 [%0], %1;" :: "r"((uint32_t)(addr)), "r"((uint32_t)(cnt)) : "memory")
#define MBARRIER_ARRIVE(addr) \
    asm volatile("mbarrier.arrive.shared.b64 _, [%0];" :: "r"((uint32_t)(addr)) : "memory")
#define MBARRIER_EXPECT_TX(addr, tx) \
    asm volatile("mbarrier.arrive.expect_tx.shared.b64 _, [%0], %1;" :: "r"((uint32_t)(addr)), "r"((uint32_t)(tx)) : "memory")
#define MBARRIER_WAIT_PARITY(addr, parity) do { \
    uint32_t _m = (uint32_t)(addr); uint32_t _p = (uint32_t)(parity); uint32_t _d; \
    asm volatile("{\n\t.reg .pred p;\n\t" \
        "mbarrier.try_wait.parity.acquire.cta.shared::cta.b64 p, [%1], %2;\n\t" \
        "selp.b32 %0, 1, 0, p;\n\t}" : "=r"(_d) : "r"(_m), "r"(_p) : "memory"); \
    if (!_d) { \
        asm volatile("{\n\t.reg .pred P1;\n\t" \
            "WL_%=:\n\t" \
            "mbarrier.try_wait.parity.acquire.cta.shared::cta.b64 P1, [%0], %1, 0x989680;\n\t" \
            "@P1 bra.uni WD_%=;\n\t" \
            "bra.uni WL_%=;\n\t" \
            "WD_%=:\n\t}" :: "r"(_m), "r"(_p) : "memory"); \
    } \
} while (0)

__device__ __forceinline__ uint32_t pack2(float a, float b) {
    __half2 h = __floats2half2_rn(a, b);
    return *reinterpret_cast<uint32_t*>(&h);
}
// legacy fp16 mma (always available)
__device__ __forceinline__ void mma_f16(float* c, const uint32_t* a, const uint32_t* b) {
    asm volatile(
        "mma.sync.aligned.m16n8k16.row.col.f32.f16.f16.f32 "
        "{%0,%1,%2,%3}, {%4,%5,%6,%7}, {%8,%9}, {%0,%1,%2,%3};\n"
        : "+f"(c[0]), "+f"(c[1]), "+f"(c[2]), "+f"(c[3])
        : "r"(a[0]), "r"(a[1]), "r"(a[2]), "r"(a[3]), "r"(b[0]), "r"(b[1]));
}

static constexpr uint64_t SMEM_DESC_BASE_SW128 =
    (uint64_t(2) << 61) | (uint64_t(1) << 46) | (uint64_t(64) << 32) | (uint64_t(1) << 16);
#define MAKE_SMEM_DESC(a) (SMEM_DESC_BASE_SW128 | ((uint64_t)((a) >> 4) & 0x3FFF))

// ===========================================================================
__global__ void probe_kernel() {
#if HAS_TC
    if (threadIdx.x == 0) g_tc_done = 1;
#else
    if (threadIdx.x == 0) g_tc_done = 0;
#endif
}

__global__ void zero_counts_kernel() {
    if (threadIdx.x < NEXP) g_counts[threadIdx.x] = 0;
}

// Router: one warp per token (verbatim from R1 — validated)
__global__ void router_kernel(const float* __restrict__ x,
                              const float* __restrict__ Wr) {
    __shared__ float sWr[NEXP][1024];
    int tid = threadIdx.x;
    for (int i = tid; i < 1024 * NEXP; i += blockDim.x) {
        int d = i >> 3, e = i & 7;
        sWr[e][d] = Wr[i];
    }
    __syncthreads();
    int warp = tid >> 5, lane = tid & 31;
    int token = blockIdx.x * 8 + warp;
    if (token >= T_TOK) return;
    const float* xr = x + (size_t)token * 1024;
    float acc[NEXP];
#pragma unroll
    for (int e = 0; e < NEXP; e++) acc[e] = 0.f;
    for (int i = lane; i < 1024; i += 32) {
        float xv = xr[i];
#pragma unroll
        for (int e = 0; e < NEXP; e++) acc[e] += xv * sWr[e][i];
    }
#pragma unroll
    for (int e = 0; e < NEXP; e++)
#pragma unroll
        for (int off = 16; off > 0; off >>= 1)
            acc[e] += __shfl_xor_sync(0xffffffffu, acc[e], off);
    if (lane == 0) {
        float mx = acc[0];
#pragma unroll
        for (int e = 1; e < NEXP; e++) mx = fmaxf(mx, acc[e]);
        float p[NEXP], s = 0.f;
#pragma unroll
        for (int e = 0; e < NEXP; e++) { p[e] = expf(acc[e] - mx); s += p[e]; }
        float inv = 1.f / s;
#pragma unroll
        for (int e = 0; e < NEXP; e++) p[e] *= inv;
        int i0 = 0; float b0 = p[0];
#pragma unroll
        for (int e = 1; e < NEXP; e++) if (p[e] > b0) { b0 = p[e]; i0 = e; }
        int i1 = -1; float b1 = -1.f;
#pragma unroll
        for (int e = 0; e < NEXP; e++)
            if (e != i0 && p[e] > b1) { b1 = p[e]; i1 = e; }
        int s0 = token * 2, s1 = token * 2 + 1;
        g_gates[s0] = b0;
        g_gates[s1] = b1;
        int pos0 = atomicAdd(&g_counts[i0], 1);
        g_lists[i0 * CAP + pos0] = s0;
        int pos1 = atomicAdd(&g_counts[i1], 1);
        g_lists[i1 * CAP + pos1] = s1;
    }
}

// Transpose + fp16-convert weights: [e][k][n] fp32 -> [mat*8+e][n][k] fp16
__global__ void transpose_half_kernel(const float* __restrict__ Wi,
                                      const float* __restrict__ Wo) {
    __shared__ float t[32][33];
    int mat = blockIdx.z >> 3, e = blockIdx.z & 7;
    const float* src = (mat ? Wo : Wi) + (size_t)e * 1024 * 1024;
    __half* dst = g_wt16 + (size_t)blockIdx.z * 1024 * 1024;
    int k0 = blockIdx.y * 32, n0 = blockIdx.x * 32;
    int tx = threadIdx.x, ty = threadIdx.y;
#pragma unroll
    for (int i = 0; i < 4; i++)
        t[ty + 8 * i][tx] = src[(size_t)(k0 + ty + 8 * i) * 1024 + n0 + tx];
    __syncthreads();
#pragma unroll
    for (int i = 0; i < 4; i++) {
        int n = ty + 8 * i;
        dst[(size_t)(n0 + n) * 1024 + k0 + tx] = __float2half_rn(t[tx][n]);
    }
}

// ===========================================================================
// tcgen05 fp16 grouped GEMM (feature-gated body). Same pipeline as R2 design.
template <int STAGE>
__global__ __launch_bounds__(192, 1)
void moe_tc_gemm(const float* __restrict__ x) {
#if HAS_TC
    extern __shared__ char smem[];
    const int e = blockIdx.z;
    const int cnt = g_counts[e];
    const int m0 = blockIdx.y * TM;
    if (m0 >= cnt) return;
    const int n0 = blockIdx.x * TN;
    const uint32_t sb = smem_u32(smem);
    const int tid = threadIdx.x, wid = tid >> 5;

    if (tid == 0) {
#pragma unroll
        for (int s = 0; s < NST; s++) {
            MBARRIER_INIT(sb + SM_FULL + 8 * s, 129);   // 128 A-arrives + 1 expect_tx
            MBARRIER_INIT(sb + SM_EMPTY + 8 * s, 1);    // 1 tcgen05.commit
        }
        MBARRIER_INIT(sb + SM_DONE, 1);
    }
    if (wid == 5)
        asm volatile("tcgen05.alloc.cta_group::1.sync.aligned.shared::cta.b32 [%0], %1;"
                     :: "r"(sb + SM_TMEM), "r"(256u) : "memory");
    __syncthreads();
    uint32_t tmem;
    asm volatile("ld.shared.b32 %0, [%1];" : "=r"(tmem) : "r"(sb + SM_TMEM));

    const float* Asrc = (STAGE == 1) ? x : g_h;
    float* Cdst = (STAGE == 1) ? g_h : g_o;
    const int* lst = g_lists + e * CAP + m0;

    if (wid < 4) {
        // ---- A producer: 128 threads; seg = 16B unit (8 halves), 8 rows each
        const int seg = tid & 7;
        const float* rp[8];
#pragma unroll
        for (int i = 0; i < 8; i++) {
            int r = (tid >> 3) + 16 * i;
            if (m0 + r < cnt) {
                int slot = lst[r];
                size_t row = (STAGE == 1) ? (size_t)(slot >> 1) : (size_t)slot;
                rp[i] = Asrc + row * 1024 + seg * 8;
            } else {
                rp[i] = nullptr;
            }
        }
        int ph = 1;
        for (int c = 0; c < NCHUNK; c++) {
            int s = c & (NST - 1);
            MBARRIER_WAIT_PARITY(sb + SM_EMPTY + 8 * s, ph);
            char* ab = smem + SM_A + s * A_TILE_B;
            int ko = c * KC;
#pragma unroll
            for (int i = 0; i < 8; i++) {
                float4 u0 = rp[i] ? *(const float4*)(rp[i] + ko)
                                  : make_float4(0.f, 0.f, 0.f, 0.f);
                float4 u1 = rp[i] ? *(const float4*)(rp[i] + ko + 4)
                                  : make_float4(0.f, 0.f, 0.f, 0.f);
                int r = (tid >> 3) + 16 * i;
                uint32_t bo = (uint32_t)(r * 128 + seg * 16);
                bo ^= (bo >> 3) & 0x70;
                uint4 w;
                w.x = pack2(u0.x, u0.y);
                w.y = pack2(u0.z, u0.w);
                w.z = pack2(u1.x, u1.y);
                w.w = pack2(u1.z, u1.w);
                *(uint4*)(ab + bo) = w;
            }
            asm volatile("fence.proxy.async.shared::cta;" ::: "memory");
            MBARRIER_ARRIVE(sb + SM_FULL + 8 * s);
            if (s == NST - 1) ph ^= 1;
        }

        // ---- Epilogue
        MBARRIER_WAIT_PARITY(sb + SM_DONE, 0);
        asm volatile("tcgen05.fence::after_thread_sync;" ::: "memory");
        const int rr = tid;
        bool val = (m0 + rr) < cnt;
        int slot = val ? lst[rr] : 0;
        float gate = (STAGE == 2) ? (val ? g_gates[slot] : 0.f) : 1.f;
        float* crow = Cdst + (size_t)slot * 1024 + n0;
#pragma unroll
        for (int cb = 0; cb < 8; cb++) {
            uint32_t regs[32];
            asm volatile("tcgen05.ld.sync.aligned.32x32b.x32.b32 "
                "{%0,%1,%2,%3,%4,%5,%6,%7,%8,%9,%10,%11,%12,%13,%14,%15,"
                "%16,%17,%18,%19,%20,%21,%22,%23,%24,%25,%26,%27,%28,%29,%30,%31}, [%32];"
                : "=r"(regs[0]),"=r"(regs[1]),"=r"(regs[2]),"=r"(regs[3]),
                  "=r"(regs[4]),"=r"(regs[5]),"=r"(regs[6]),"=r"(regs[7]),
                  "=r"(regs[8]),"=r"(regs[9]),"=r"(regs[10]),"=r"(regs[11]),
                  "=r"(regs[12]),"=r"(regs[13]),"=r"(regs[14]),"=r"(regs[15]),
                  "=r"(regs[16]),"=r"(regs[17]),"=r"(regs[18]),"=r"(regs[19]),
                  "=r"(regs[20]),"=r"(regs[21]),"=r"(regs[22]),"=r"(regs[23]),
                  "=r"(regs[24]),"=r"(regs[25]),"=r"(regs[26]),"=r"(regs[27]),
                  "=r"(regs[28]),"=r"(regs[29]),"=r"(regs[30]),"=r"(regs[31])
                : "r"(tmem + cb * 32));
            asm volatile("tcgen05.wait::ld.sync.aligned;" ::: "memory");
            if (val) {
#pragma unroll
                for (int q = 0; q < 8; q++) {
                    float4 o;
                    o.x = __uint_as_float(regs[q * 4 + 0]) * gate;
                    o.y = __uint_as_float(regs[q * 4 + 1]) * gate;
                    o.z = __uint_as_float(regs[q * 4 + 2]) * gate;
                    o.w = __uint_as_float(regs[q * 4 + 3]) * gate;
                    *(float4*)(crow + cb * 32 + q * 4) = o;
                }
            }
        }
    } else if (wid == 4) {
        // ---- TMA B producer
        if (elect_one_pred()) {
            const CUtensorMap* tm = &g_tmap;
            int zc = (STAGE == 1) ? e : NEXP + e;
            int ph = 1;
            for (int c = 0; c < NCHUNK; c++) {
                int s = c & (NST - 1);
                MBARRIER_WAIT_PARITY(sb + SM_EMPTY + 8 * s, ph);
                MBARRIER_EXPECT_TX(sb + SM_FULL + 8 * s, B_TILE_B);
                asm volatile("cp.async.bulk.tensor.3d.shared::cta.global.tile.mbarrier::complete_tx::bytes "
                    "[%0], [%1, {%2, %3, %4}], [%5];"
                    :: "r"(sb + SM_B + s * B_TILE_B), "l"(tm),
                       "r"(c * KC), "r"(n0), "r"(zc),
                       "r"(sb + SM_FULL + 8 * s) : "memory");
                if (s == NST - 1) ph ^= 1;
            }
        }
    } else {
        // ---- MMA warp (5)
        if (elect_one_pred()) {
            int ph = 0;
            for (int c = 0; c < NCHUNK; c++) {
                int s = c & (NST - 1);
                MBARRIER_WAIT_PARITY(sb + SM_FULL + 8 * s, ph);
                uint64_t ad = MAKE_SMEM_DESC(sb + SM_A + s * A_TILE_B);
                uint64_t bd = MAKE_SMEM_DESC(sb + SM_B + s * B_TILE_B);
#pragma unroll
                for (int sub = 0; sub < 4; sub++) {
                    uint32_t en = (unsigned)((c | sub) != 0);
                    asm volatile("{\n\t.reg .pred p;\n\tsetp.ne.u32 p, %6, 0;\n\t"
                        "tcgen05.mma.cta_group::1.kind::f16 [%0], %1, %2, %3, "
                        "{%4, %4, %4, %4}, p;\n\t}"
                        :: "r"(tmem), "l"(ad + 2 * sub), "l"(bd + 2 * sub),
                           "r"(IDESC), "r"(0u), "r"(0u), "r"(en) : "memory");
                }
                asm volatile("tcgen05.commit.cta_group::1.mbarrier::arrive::one.shared::cluster.b64 [%0];"
                             :: "r"(sb + SM_EMPTY + 8 * s) : "memory");
                if (s == NST - 1) ph ^= 1;
            }
            asm volatile("tcgen05.commit.cta_group::1.mbarrier::arrive::one.shared::cluster.b64 [%0];"
                         :: "r"(sb + SM_DONE) : "memory");
        }
    }

    __syncthreads();
    if (wid == 5) {
        asm volatile("tcgen05.relinquish_alloc_permit.cta_group::1.sync.aligned;");
        asm volatile("tcgen05.dealloc.cta_group::1.sync.aligned.b32 %0, %1;" :: "r"(tmem), "r"(256u));
    }
#endif  // HAS_TC
}

// ===========================================================================
// Fallback fp16 mma.sync GEMM (always compiled). Skipped if tcgen05 ran.
// BM=128, BN=256, BK=32 (16 fp16 pairs). 8 warps, warp tile 64x64.
template <int STAGE>
__global__ __launch_bounds__(256, 1)
void moe_fb_gemm(const float* __restrict__ x) {
    if (g_tc_done) return;
    const int e = blockIdx.z;
    const int cnt = g_counts[e];
    const int m0 = blockIdx.y * 128;
    if (m0 >= cnt) return;
    const int n0 = blockIdx.x * 256;

    const float* Asrc = (STAGE == 1) ? x : g_h;
    float* Cdst = (STAGE == 1) ? g_h : g_o;
    const __half* B = g_wt16 + (size_t)((STAGE == 1 ? 0 : 8) + e) * 1024 * 1024;
    const int* lst = g_lists + e * CAP + m0;

    __shared__ uint32_t sA32[128 * 20];   // [row][pair], pad 20 (conflict-free)
    __shared__ uint32_t sB32[256 * 20];   // [n][pair]

    const int tid = threadIdx.x;
    // A loader: rows (tid>>3)+32p, seg tid&7 -> floats 4seg..4seg+3
    const int arow = tid >> 3, aseg = tid & 7;
    const float* aptr[4];
#pragma unroll
    for (int p = 0; p < 4; p++) {
        int r = arow + 32 * p;
        if (m0 + r < cnt) {
            int slot = lst[r];
            size_t row = (STAGE == 1) ? (size_t)(slot >> 1) : (size_t)slot;
            aptr[p] = Asrc + row * 1024 + aseg * 4;
        } else {
            aptr[p] = nullptr;
        }
    }
    // B loader: rows (tid>>2)+64p, seg tid&3 -> halves 8seg..8seg+7
    const int brow = tid >> 2, bseg = tid & 3;
    const __half* brp[4];
#pragma unroll
    for (int p = 0; p < 4; p++)
        brp[p] = B + (size_t)(n0 + brow + 64 * p) * 1024 + bseg * 8;

    const int warp = tid >> 5, lane = tid & 31;
    const int wm = warp & 1, wn = warp >> 1;     // 2 x 4 warps of 64x64
    const int g = lane >> 2, tg = lane & 3;

    float c[4][8][4];
#pragma unroll
    for (int i = 0; i < 4; i++)
#pragma unroll
        for (int j = 0; j < 8; j++)
#pragma unroll
            for (int q = 0; q < 4; q++) c[i][j][q] = 0.f;

    float4 aReg[4];
    uint4 bReg[4];
#pragma unroll
    for (int p = 0; p < 4; p++)
        aReg[p] = aptr[p] ? *(const float4*)(aptr[p]) : make_float4(0.f, 0.f, 0.f, 0.f);
#pragma unroll
    for (int p = 0; p < 4; p++)
        bReg[p] = *(const uint4*)(brp[p]);

    for (int kt = 0; kt < 32; kt++) {
        if (kt) __syncthreads();
        // stage A (fp32 -> fp16 pairs)
#pragma unroll
        for (int p = 0; p < 4; p++) {
            int r = arow + 32 * p;
            uint2 w;
            w.x = pack2(aReg[p].x, aReg[p].y);
            w.y = pack2(aReg[p].z, aReg[p].w);
            *(uint2*)&sA32[r * 20 + 2 * aseg] = w;
        }
        // stage B (already fp16, 4 pairs contiguous)
#pragma unroll
        for (int p = 0; p < 4; p++) {
            int n = brow + 64 * p;
            *(uint4*)&sB32[n * 20 + 4 * bseg] = bReg[p];
        }
        __syncthreads();

        if (kt < 31) {
            int ko = (kt + 1) * 32;
#pragma unroll
            for (int p = 0; p < 4; p++)
                aReg[p] = aptr[p] ? *(const float4*)(aptr[p] + ko)
                                  : make_float4(0.f, 0.f, 0.f, 0.f);
#pragma unroll
            for (int p = 0; p < 4; p++)
                bReg[p] = *(const uint4*)(brp[p] + ko);
        }

#pragma unroll
        for (int ks = 0; ks < 2; ks++) {
            const int kp = 8 * ks;
            uint32_t a[4][4], b[8][2];
#pragma unroll
            for (int mf = 0; mf < 4; mf++) {
                int row = wm * 64 + mf * 16 + g;
                a[mf][0] = sA32[row * 20 + kp + tg];
                a[mf][1] = sA32[(row + 8) * 20 + kp + tg];
                a[mf][2] = sA32[row * 20 + kp + tg + 4];
                a[mf][3] = sA32[(row + 8) * 20 + kp + tg + 4];
            }
#pragma unroll
            for (int nf = 0; nf < 8; nf++) {
                int n = wn * 64 + nf * 8 + g;
                b[nf][0] = sB32[n * 20 + kp + tg];
                b[nf][1] = sB32[n * 20 + kp + tg + 4];
            }
#pragma unroll
            for (int mf = 0; mf < 4; mf++)
#pragma unroll
                for (int nf = 0; nf < 8; nf++)
                    mma_f16(c[mf][nf], a[mf], b[nf]);
        }
    }

    // epilogue
#pragma unroll
    for (int mf = 0; mf < 4; mf++) {
#pragma unroll
        for (int half = 0; half < 2; half++) {
            int r = wm * 64 + mf * 16 + g + half * 8;
            if (m0 + r >= cnt) continue;
            int slot = lst[r];
            float gate = (STAGE == 2) ? g_gates[slot] : 1.0f;
            float* crow = Cdst + (size_t)slot * 1024 + n0;
#pragma unroll
            for (int nf = 0; nf < 8; nf++) {
                int cc = wn * 64 + nf * 8 + tg * 2;
                float2 v;
                v.x = c[mf][nf][half * 2 + 0] * gate;
                v.y = c[mf][nf][half * 2 + 1] * gate;
                *(float2*)(crow + cc) = v;
            }
        }
    }
}

// out[t] = o[2t] + o[2t+1]
__global__ void combine_kernel(float* __restrict__ out) {
    size_t i = (size_t)blockIdx.x * blockDim.x + threadIdx.x;
    size_t t = i >> 8, cc = i & 255;
    const float4* o4 = (const float4*)g_o;
    float4 a = o4[(t * 2) * 256 + cc];
    float4 b = o4[(t * 2 + 1) * 256 + cc];
    float4 r;
    r.x = a.x + b.x; r.y = a.y + b.y; r.z = a.z + b.z; r.w = a.w + b.w;
    ((float4*)out)[i] = r;
}

// ===========================================================================
typedef CUresult (*tmap_encode_fn)(
    CUtensorMap*, CUtensorMapDataType, cuuint32_t, void*,
    const cuuint64_t*, const cuuint64_t*, const cuuint32_t*, const cuuint32_t*,
    CUtensorMapInterleave, CUtensorMapSwizzle, CUtensorMapL2promotion,
    CUtensorMapFloatOOBfill);

extern "C" void kernel_launch(void* const* d_in, const int* in_sizes, int n_in,
                              void* d_out, int out_size) {
    const float* x  = (const float*)d_in[0];
    const float* Wr = (const float*)d_in[1];
    const float* Wi = (const float*)d_in[2];
    const float* Wo = (const float*)d_in[3];
    float* out = (float*)d_out;
    (void)in_sizes; (void)n_in; (void)out_size;

    // Tensormap for g_wt16: [16][n=1024][k=1024] fp16, SW128, box (64,256,1)
    void* fnp = nullptr;
    cudaDriverEntryPointQueryResult qr;
    cudaGetDriverEntryPoint("cuTensorMapEncodeTiled", &fnp, cudaEnableDefault, &qr);
    if (fnp) {
        void* wt_ptr = nullptr;
        cudaGetSymbolAddress(&wt_ptr, g_wt16);
        static CUtensorMap h_tmap;
        cuuint64_t dims[3]    = {1024, 1024, 16};
        cuuint64_t strides[2] = {2048, 2048ull * 1024};
        cuuint32_t box[3]     = {64, 256, 1};
        cuuint32_t es[3]      = {1, 1, 1};
        ((tmap_encode_fn)fnp)(&h_tmap, CU_TENSOR_MAP_DATA_TYPE_FLOAT16, 3, wt_ptr,
                              dims, strides, box, es,
                              CU_TENSOR_MAP_INTERLEAVE_NONE, CU_TENSOR_MAP_SWIZZLE_128B,
                              CU_TENSOR_MAP_L2_PROMOTION_L2_128B,
                              CU_TENSOR_MAP_FLOAT_OOB_FILL_NONE);
        cudaMemcpyToSymbolAsync(g_tmap, &h_tmap, sizeof(CUtensorMap), 0,
                                cudaMemcpyHostToDevice, 0);
    }

    cudaFuncSetAttribute(moe_tc_gemm<1>, cudaFuncAttributeMaxDynamicSharedMemorySize, SMEM_TOTAL);
    cudaFuncSetAttribute(moe_tc_gemm<2>, cudaFuncAttributeMaxDynamicSharedMemorySize, SMEM_TOTAL);

    probe_kernel<<<1, 32>>>();
    zero_counts_kernel<<<1, 32>>>();
    router_kernel<<<T_TOK / 8, 256>>>(x, Wr);
    transpose_half_kernel<<<dim3(32, 32, 16), dim3(32, 8)>>>(Wi, Wo);

    dim3 g(1024 / TN, CAP / TM, NEXP);   // (4, 128, 8)
    moe_tc_gemm<1><<<g, 192, SMEM_TOTAL>>>(x);
    moe_fb_gemm<1><<<g, 256>>>(x);
    moe_tc_gemm<2><<<g, 192, SMEM_TOTAL>>>(x);
    moe_fb_gemm<2><<<g, 256>>>(x);

    combine_kernel<<<(T_TOK * 1024 / 4) / 256, 256>>>(out);
}

// round 4
// speedup vs baseline: 2.5279x; 1.3460x over previous
#include <cuda_runtime.h>
#include <cuda.h>
#include <cuda_fp16.h>
#include <cstdint>

// ===========================================================================
#if defined(__CUDA_ARCH_FEAT_SM100_ALL) || defined(__CUDA_ARCH_FEAT_SM103_ALL)
#define HAS_TC 1
#else
#define HAS_TC 0
#endif

#define T_TOK 8192
#define NEXP  8
#define NSLOT (T_TOK*2)
#define CAP   NSLOT
#define ECAP  8192           // per-expert max rows (each token -> expert at most once)

// tcgen05 tiling: fp16, chunk = 64 halves = 128B row
#define NST   4
#define KC    64
#define NCHUNK 16
#define TM    128
#define TN    256
#define A_TILE_B (TM*128)    // 16 KB
#define B_TILE_B (TN*128)    // 32 KB
#define SM_TMEM  0
#define SM_FULL  64
#define SM_EMPTY 128
#define SM_DONE  192
#define SM_A     1024
#define SM_B     (SM_A + NST*A_TILE_B)
#define SMEM_TOTAL (SM_B + NST*B_TILE_B)   // 197632

#define IDESC ((1u<<4)|((unsigned)(TN/8)<<17)|((unsigned)(TM/16)<<24))

// ===========================================================================
// Device scratch
__device__ __half g_xs[(size_t)NEXP * ECAP * 1024];   // 128 MB sorted fp16 x
__device__ __half g_hs[(size_t)NEXP * ECAP * 1024];   // 128 MB sorted fp16 h
__device__ float  g_o[(size_t)NSLOT * 1024];          // 64 MB stage-2 out
__device__ __half g_wt16[(size_t)16 * 1024 * 1024];   // [mat*8+e][n][k] fp16
__device__ float  g_gates[NSLOT];
__device__ int    g_lists[NEXP * CAP];
__device__ int    g_counts[NEXP];
__device__ int    g_tc_done;
__device__ __align__(128) CUtensorMap g_tmA1;   // g_xs
__device__ __align__(128) CUtensorMap g_tmA2;   // g_hs
__device__ __align__(128) CUtensorMap g_tmB;    // g_wt16

// ===========================================================================
__device__ __forceinline__ uint32_t smem_u32(const void* p) {
    uint32_t a;
    asm("{ .reg .u64 t; cvta.to.shared.u64 t, %1; cvt.u32.u64 %0, t; }" : "=r"(a) : "l"(p));
    return a;
}
__device__ __forceinline__ uint32_t elect_one_pred() {
    uint32_t p;
    asm volatile("{\n\t.reg .pred p;\n\telect.sync _|p, 0xFFFFFFFF;\n\t"
                 "selp.b32 %0, 1, 0, p;\n\t}" : "=r"(p));
    return p;
}
#define MBARRIER_INIT(addr, cnt) \
    asm volatile("mbarrier.init.shared.b64 [%0], %1;" :: "r"((uint32_t)(addr)), "r"((uint32_t)(cnt)) : "memory")
#define MBARRIER_EXPECT_TX(addr, tx) \
    asm volatile("mbarrier.arrive.expect_tx.shared.b64 _, [%0], %1;" :: "r"((uint32_t)(addr)), "r"((uint32_t)(tx)) : "memory")
#define MBARRIER_WAIT_PARITY(addr, parity) do { \
    uint32_t _m = (uint32_t)(addr); uint32_t _p = (uint32_t)(parity); uint32_t _d; \
    asm volatile("{\n\t.reg .pred p;\n\t" \
        "mbarrier.try_wait.parity.acquire.cta.shared::cta.b64 p, [%1], %2;\n\t" \
        "selp.b32 %0, 1, 0, p;\n\t}" : "=r"(_d) : "r"(_m), "r"(_p) : "memory"); \
    if (!_d) { \
        asm volatile("{\n\t.reg .pred P1;\n\t" \
            "WL_%=:\n\t" \
            "mbarrier.try_wait.parity.acquire.cta.shared::cta.b64 P1, [%0], %1, 0x989680;\n\t" \
            "@P1 bra.uni WD_%=;\n\t" \
            "bra.uni WL_%=;\n\t" \
            "WD_%=:\n\t}" :: "r"(_m), "r"(_p) : "memory"); \
    } \
} while (0)

__device__ __forceinline__ uint32_t pack2(float a, float b) {
    __half2 h = __floats2half2_rn(a, b);
    return *reinterpret_cast<uint32_t*>(&h);
}
__device__ __forceinline__ void mma_f16(float* c, const uint32_t* a, const uint32_t* b) {
    asm volatile(
        "mma.sync.aligned.m16n8k16.row.col.f32.f16.f16.f32 "
        "{%0,%1,%2,%3}, {%4,%5,%6,%7}, {%8,%9}, {%0,%1,%2,%3};\n"
        : "+f"(c[0]), "+f"(c[1]), "+f"(c[2]), "+f"(c[3])
        : "r"(a[0]), "r"(a[1]), "r"(a[2]), "r"(a[3]), "r"(b[0]), "r"(b[1]));
}

static constexpr uint64_t SMEM_DESC_BASE_SW128 =
    (uint64_t(2) << 61) | (uint64_t(1) << 46) | (uint64_t(64) << 32) | (uint64_t(1) << 16);
#define MAKE_SMEM_DESC(a) (SMEM_DESC_BASE_SW128 | ((uint64_t)((a) >> 4) & 0x3FFF))

// ===========================================================================
__global__ void init_kernel() {
    if (threadIdx.x < NEXP) g_counts[threadIdx.x] = 0;
#if HAS_TC
    if (threadIdx.x == 0) g_tc_done = 1;
#else
    if (threadIdx.x == 0) g_tc_done = 0;
#endif
}

// Router (validated R1)
__global__ void router_kernel(const float* __restrict__ x,
                              const float* __restrict__ Wr) {
    __shared__ float sWr[NEXP][1024];
    int tid = threadIdx.x;
    for (int i = tid; i < 1024 * NEXP; i += blockDim.x) {
        int d = i >> 3, e = i & 7;
        sWr[e][d] = Wr[i];
    }
    __syncthreads();
    int warp = tid >> 5, lane = tid & 31;
    int token = blockIdx.x * 8 + warp;
    if (token >= T_TOK) return;
    const float* xr = x + (size_t)token * 1024;
    float acc[NEXP];
#pragma unroll
    for (int e = 0; e < NEXP; e++) acc[e] = 0.f;
    for (int i = lane; i < 1024; i += 32) {
        float xv = xr[i];
#pragma unroll
        for (int e = 0; e < NEXP; e++) acc[e] += xv * sWr[e][i];
    }
#pragma unroll
    for (int e = 0; e < NEXP; e++)
#pragma unroll
        for (int off = 16; off > 0; off >>= 1)
            acc[e] += __shfl_xor_sync(0xffffffffu, acc[e], off);
    if (lane == 0) {
        float mx = acc[0];
#pragma unroll
        for (int e = 1; e < NEXP; e++) mx = fmaxf(mx, acc[e]);
        float p[NEXP], s = 0.f;
#pragma unroll
        for (int e = 0; e < NEXP; e++) { p[e] = expf(acc[e] - mx); s += p[e]; }
        float inv = 1.f / s;
#pragma unroll
        for (int e = 0; e < NEXP; e++) p[e] *= inv;
        int i0 = 0; float b0 = p[0];
#pragma unroll
        for (int e = 1; e < NEXP; e++) if (p[e] > b0) { b0 = p[e]; i0 = e; }
        int i1 = -1; float b1 = -1.f;
#pragma unroll
        for (int e = 0; e < NEXP; e++)
            if (e != i0 && p[e] > b1) { b1 = p[e]; i1 = e; }
        int s0 = token * 2, s1 = token * 2 + 1;
        g_gates[s0] = b0;
        g_gates[s1] = b1;
        int pos0 = atomicAdd(&g_counts[i0], 1);
        g_lists[i0 * CAP + pos0] = s0;
        int pos1 = atomicAdd(&g_counts[i1], 1);
        g_lists[i1 * CAP + pos1] = s1;
    }
}

// Weights: [e][k][n] fp32 -> [mat*8+e][n][k] fp16
__global__ void transpose_half_kernel(const float* __restrict__ Wi,
                                      const float* __restrict__ Wo) {
    __shared__ float t[32][33];
    int mat = blockIdx.z >> 3, e = blockIdx.z & 7;
    const float* src = (mat ? Wo : Wi) + (size_t)e * 1024 * 1024;
    __half* dst = g_wt16 + (size_t)blockIdx.z * 1024 * 1024;
    int k0 = blockIdx.y * 32, n0 = blockIdx.x * 32;
    int tx = threadIdx.x, ty = threadIdx.y;
#pragma unroll
    for (int i = 0; i < 4; i++)
        t[ty + 8 * i][tx] = src[(size_t)(k0 + ty + 8 * i) * 1024 + n0 + tx];
    __syncthreads();
#pragma unroll
    for (int i = 0; i < 4; i++) {
        int n = ty + 8 * i;
        dst[(size_t)(n0 + n) * 1024 + k0 + tx] = __float2half_rn(t[tx][n]);
    }
}

// Expert-sorted fp16 gather of x: g_xs[e][pos] = fp16(x[token(slot)])
__global__ void gather_x_kernel(const float* __restrict__ x) {
    int e = blockIdx.y;
    int pos = blockIdx.x;
    if (pos >= g_counts[e]) return;
    int slot = g_lists[e * CAP + pos];
    int token = slot >> 1;
    const float4* src = (const float4*)(x + (size_t)token * 1024);
    uint4* dst = (uint4*)(g_xs + ((size_t)(e * ECAP + pos)) * 1024);
    int t = threadIdx.x;   // 128
    float4 a = src[2 * t], b = src[2 * t + 1];
    uint4 w;
    w.x = pack2(a.x, a.y); w.y = pack2(a.z, a.w);
    w.z = pack2(b.x, b.y); w.w = pack2(b.z, b.w);
    dst[t] = w;
}

// ===========================================================================
// Pure-TMA tcgen05 fp16 grouped GEMM.
// STAGE 1: A = g_xs (TMA), B = Wi16 -> g_hs fp16 (sorted)
// STAGE 2: A = g_hs (TMA), B = Wo16 -> g_o fp32 * gate (scatter by slot)
template <int STAGE>
__global__ __launch_bounds__(192, 1)
void moe_tc_gemm() {
#if HAS_TC
    extern __shared__ char smem[];
    const int e = blockIdx.z;
    const int cnt = g_counts[e];
    const int m0 = blockIdx.y * TM;
    if (m0 >= cnt) return;
    const int n0 = blockIdx.x * TN;
    const uint32_t sb = smem_u32(smem);
    const int tid = threadIdx.x, wid = tid >> 5;

    if (tid == 0) {
#pragma unroll
        for (int s = 0; s < NST; s++) {
            MBARRIER_INIT(sb + SM_FULL + 8 * s, 1);    // 1 expect_tx (A+B bytes)
            MBARRIER_INIT(sb + SM_EMPTY + 8 * s, 1);   // 1 tcgen05.commit
        }
        MBARRIER_INIT(sb + SM_DONE, 1);
    }
    if (wid == 5)
        asm volatile("tcgen05.alloc.cta_group::1.sync.aligned.shared::cta.b32 [%0], %1;"
                     :: "r"(sb + SM_TMEM), "r"(256u) : "memory");
    __syncthreads();
    uint32_t tmem;
    asm volatile("ld.shared.b32 %0, [%1];" : "=r"(tmem) : "r"(sb + SM_TMEM));

    if (wid == 4) {
        // ---- TMA producer: A + B per chunk, one barrier ----
        if (elect_one_pred()) {
            const CUtensorMap* tmA = (STAGE == 1) ? &g_tmA1 : &g_tmA2;
            const CUtensorMap* tmB = &g_tmB;
            int zb = (STAGE == 1) ? e : NEXP + e;
            int ph = 1;
            for (int c = 0; c < NCHUNK; c++) {
                int s = c & (NST - 1);
                MBARRIER_WAIT_PARITY(sb + SM_EMPTY + 8 * s, ph);
                MBARRIER_EXPECT_TX(sb + SM_FULL + 8 * s, A_TILE_B + B_TILE_B);
                asm volatile("cp.async.bulk.tensor.3d.shared::cta.global.tile.mbarrier::complete_tx::bytes "
                    "[%0], [%1, {%2, %3, %4}], [%5];"
                    :: "r"(sb + SM_A + s * A_TILE_B), "l"(tmA),
                       "r"(c * KC), "r"(m0), "r"(e),
                       "r"(sb + SM_FULL + 8 * s) : "memory");
                asm volatile("cp.async.bulk.tensor.3d.shared::cta.global.tile.mbarrier::complete_tx::bytes "
                    "[%0], [%1, {%2, %3, %4}], [%5];"
                    :: "r"(sb + SM_B + s * B_TILE_B), "l"(tmB),
                       "r"(c * KC), "r"(n0), "r"(zb),
                       "r"(sb + SM_FULL + 8 * s) : "memory");
                if (s == NST - 1) ph ^= 1;
            }
        }
    } else if (wid == 5) {
        // ---- MMA warp ----
        if (elect_one_pred()) {
            int ph = 0;
            for (int c = 0; c < NCHUNK; c++) {
                int s = c & (NST - 1);
                MBARRIER_WAIT_PARITY(sb + SM_FULL + 8 * s, ph);
                uint64_t ad = MAKE_SMEM_DESC(sb + SM_A + s * A_TILE_B);
                uint64_t bd = MAKE_SMEM_DESC(sb + SM_B + s * B_TILE_B);
#pragma unroll
                for (int sub = 0; sub < 4; sub++) {
                    uint32_t en = (unsigned)((c | sub) != 0);
                    asm volatile("{\n\t.reg .pred p;\n\tsetp.ne.u32 p, %6, 0;\n\t"
                        "tcgen05.mma.cta_group::1.kind::f16 [%0], %1, %2, %3, "
                        "{%4, %4, %4, %4}, p;\n\t}"
                        :: "r"(tmem), "l"(ad + 2 * sub), "l"(bd + 2 * sub),
                           "r"(IDESC), "r"(0u), "r"(0u), "r"(en) : "memory");
                }
                asm volatile("tcgen05.commit.cta_group::1.mbarrier::arrive::one.shared::cluster.b64 [%0];"
                             :: "r"(sb + SM_EMPTY + 8 * s) : "memory");
                if (s == NST - 1) ph ^= 1;
            }
            asm volatile("tcgen05.commit.cta_group::1.mbarrier::arrive::one.shared::cluster.b64 [%0];"
                         :: "r"(sb + SM_DONE) : "memory");
        }
    }

    if (wid < 4) {
        // ---- Epilogue: lane = M row ----
        MBARRIER_WAIT_PARITY(sb + SM_DONE, 0);
        asm volatile("tcgen05.fence::after_thread_sync;" ::: "memory");
        const int rr = tid;
        bool val = (m0 + rr) < cnt;
        const int* lst = g_lists + e * CAP + m0;
        int slot = (STAGE == 2 && val) ? lst[rr] : 0;
        float gate = (STAGE == 2) ? (val ? g_gates[slot] : 0.f) : 1.f;
        float* crow32 = g_o + (size_t)slot * 1024 + n0;
        __half* crow16 = g_hs + ((size_t)(e * ECAP + m0 + rr)) * 1024 + n0;
#pragma unroll
        for (int cb = 0; cb < 8; cb++) {
            uint32_t regs[32];
            asm volatile("tcgen05.ld.sync.aligned.32x32b.x32.b32 "
                "{%0,%1,%2,%3,%4,%5,%6,%7,%8,%9,%10,%11,%12,%13,%14,%15,"
                "%16,%17,%18,%19,%20,%21,%22,%23,%24,%25,%26,%27,%28,%29,%30,%31}, [%32];"
                : "=r"(regs[0]),"=r"(regs[1]),"=r"(regs[2]),"=r"(regs[3]),
                  "=r"(regs[4]),"=r"(regs[5]),"=r"(regs[6]),"=r"(regs[7]),
                  "=r"(regs[8]),"=r"(regs[9]),"=r"(regs[10]),"=r"(regs[11]),
                  "=r"(regs[12]),"=r"(regs[13]),"=r"(regs[14]),"=r"(regs[15]),
                  "=r"(regs[16]),"=r"(regs[17]),"=r"(regs[18]),"=r"(regs[19]),
                  "=r"(regs[20]),"=r"(regs[21]),"=r"(regs[22]),"=r"(regs[23]),
                  "=r"(regs[24]),"=r"(regs[25]),"=r"(regs[26]),"=r"(regs[27]),
                  "=r"(regs[28]),"=r"(regs[29]),"=r"(regs[30]),"=r"(regs[31])
                : "r"(tmem + cb * 32));
            asm volatile("tcgen05.wait::ld.sync.aligned;" ::: "memory");
            if (val) {
                if (STAGE == 1) {
                    // fp32 -> fp16, 32 halves = 4 uint4
#pragma unroll
                    for (int q = 0; q < 4; q++) {
                        uint4 w;
                        w.x = pack2(__uint_as_float(regs[q*8+0]), __uint_as_float(regs[q*8+1]));
                        w.y = pack2(__uint_as_float(regs[q*8+2]), __uint_as_float(regs[q*8+3]));
                        w.z = pack2(__uint_as_float(regs[q*8+4]), __uint_as_float(regs[q*8+5]));
                        w.w = pack2(__uint_as_float(regs[q*8+6]), __uint_as_float(regs[q*8+7]));
                        *(uint4*)(crow16 + cb * 32 + q * 8) = w;
                    }
                } else {
#pragma unroll
                    for (int q = 0; q < 8; q++) {
                        float4 o;
                        o.x = __uint_as_float(regs[q * 4 + 0]) * gate;
                        o.y = __uint_as_float(regs[q * 4 + 1]) * gate;
                        o.z = __uint_as_float(regs[q * 4 + 2]) * gate;
                        o.w = __uint_as_float(regs[q * 4 + 3]) * gate;
                        *(float4*)(crow32 + cb * 32 + q * 4) = o;
                    }
                }
            }
        }
    }

    __syncthreads();
    if (wid == 5) {
        asm volatile("tcgen05.relinquish_alloc_permit.cta_group::1.sync.aligned;");
        asm volatile("tcgen05.dealloc.cta_group::1.sync.aligned.b32 %0, %1;" :: "r"(tmem), "r"(256u));
    }
#endif
}

// ===========================================================================
// Fallback fp16 mma.sync GEMM (always compiled; skipped when tcgen05 ran).
// Reads A from sorted fp16 buffers (g_xs / g_hs), contiguous rows.
template <int STAGE>
__global__ __launch_bounds__(256, 1)
void moe_fb_gemm() {
    if (g_tc_done) return;
    const int e = blockIdx.z;
    const int cnt = g_counts[e];
    const int m0 = blockIdx.y * 128;
    if (m0 >= cnt) return;
    const int n0 = blockIdx.x * 256;

    const __half* Asrc = ((STAGE == 1) ? g_xs : g_hs) + (size_t)e * ECAP * 1024;
    const __half* B = g_wt16 + (size_t)((STAGE == 1 ? 0 : 8) + e) * 1024 * 1024;
    const int* lst = g_lists + e * CAP + m0;

    __shared__ uint32_t sA32[128 * 20];
    __shared__ uint32_t sB32[256 * 20];

    const int tid = threadIdx.x;
    // A loader: rows (tid>>3)+32p, seg tid&7 -> halves 4seg..4seg+3 (uint2)
    const int arow = tid >> 3, aseg = tid & 7;
    const __half* aptr[4];
#pragma unroll
    for (int p = 0; p < 4; p++) {
        int r = arow + 32 * p;
        aptr[p] = (m0 + r < cnt) ? Asrc + (size_t)(m0 + r) * 1024 + aseg * 4 : nullptr;
    }
    const int brow = tid >> 2, bseg = tid & 3;
    const __half* brp[4];
#pragma unroll
    for (int p = 0; p < 4; p++)
        brp[p] = B + (size_t)(n0 + brow + 64 * p) * 1024 + bseg * 8;

    const int warp = tid >> 5, lane = tid & 31;
    const int wm = warp & 1, wn = warp >> 1;
    const int g = lane >> 2, tg = lane & 3;

    float c[4][8][4];
#pragma unroll
    for (int i = 0; i < 4; i++)
#pragma unroll
        for (int j = 0; j < 8; j++)
#pragma unroll
            for (int q = 0; q < 4; q++) c[i][j][q] = 0.f;

    uint2 aReg[4];
    uint4 bReg[4];
#pragma unroll
    for (int p = 0; p < 4; p++)
        aReg[p] = aptr[p] ? *(const uint2*)(aptr[p]) : make_uint2(0, 0);
#pragma unroll
    for (int p = 0; p < 4; p++)
        bReg[p] = *(const uint4*)(brp[p]);

    for (int kt = 0; kt < 32; kt++) {
        if (kt) __syncthreads();
#pragma unroll
        for (int p = 0; p < 4; p++) {
            int r = arow + 32 * p;
            *(uint2*)&sA32[r * 20 + 2 * aseg] = aReg[p];
        }
#pragma unroll
        for (int p = 0; p < 4; p++) {
            int n = brow + 64 * p;
            *(uint4*)&sB32[n * 20 + 4 * bseg] = bReg[p];
        }
        __syncthreads();

        if (kt < 31) {
            int ko = (kt + 1) * 32;
#pragma unroll
            for (int p = 0; p < 4; p++)
                aReg[p] = aptr[p] ? *(const uint2*)(aptr[p] + ko) : make_uint2(0, 0);
#pragma unroll
            for (int p = 0; p < 4; p++)
                bReg[p] = *(const uint4*)(brp[p] + ko);
        }

#pragma unroll
        for (int ks = 0; ks < 2; ks++) {
            const int kp = 8 * ks;
            uint32_t a[4][4], b[8][2];
#pragma unroll
            for (int mf = 0; mf < 4; mf++) {
                int row = wm * 64 + mf * 16 + g;
                a[mf][0] = sA32[row * 20 + kp + tg];
                a[mf][1] = sA32[(row + 8) * 20 + kp + tg];
                a[mf][2] = sA32[row * 20 + kp + tg + 4];
                a[mf][3] = sA32[(row + 8) * 20 + kp + tg + 4];
            }
#pragma unroll
            for (int nf = 0; nf < 8; nf++) {
                int n = wn * 64 + nf * 8 + g;
                b[nf][0] = sB32[n * 20 + kp + tg];
                b[nf][1] = sB32[n * 20 + kp + tg + 4];
            }
#pragma unroll
            for (int mf = 0; mf < 4; mf++)
#pragma unroll
                for (int nf = 0; nf < 8; nf++)
                    mma_f16(c[mf][nf], a[mf], b[nf]);
        }
    }

#pragma unroll
    for (int mf = 0; mf < 4; mf++) {
#pragma unroll
        for (int half = 0; half < 2; half++) {
            int r = wm * 64 + mf * 16 + g + half * 8;
            if (m0 + r >= cnt) continue;
            if (STAGE == 1) {
                __half* hrow = g_hs + ((size_t)(e * ECAP + m0 + r)) * 1024 + n0;
#pragma unroll
                for (int nf = 0; nf < 8; nf++) {
                    int cc = wn * 64 + nf * 8 + tg * 2;
                    *(uint32_t*)(hrow + cc) =
                        pack2(c[mf][nf][half * 2 + 0], c[mf][nf][half * 2 + 1]);
                }
            } else {
                int slot = lst[r];
                float gate = g_gates[slot];
                float* crow = g_o + (size_t)slot * 1024 + n0;
#pragma unroll
                for (int nf = 0; nf < 8; nf++) {
                    int cc = wn * 64 + nf * 8 + tg * 2;
                    float2 v;
                    v.x = c[mf][nf][half * 2 + 0] * gate;
                    v.y = c[mf][nf][half * 2 + 1] * gate;
                    *(float2*)(crow + cc) = v;
                }
            }
        }
    }
}

// out[t] = o[2t] + o[2t+1]
__global__ void combine_kernel(float* __restrict__ out) {
    size_t i = (size_t)blockIdx.x * blockDim.x + threadIdx.x;
    size_t t = i >> 8, cc = i & 255;
    const float4* o4 = (const float4*)g_o;
    float4 a = o4[(t * 2) * 256 + cc];
    float4 b = o4[(t * 2 + 1) * 256 + cc];
    float4 r;
    r.x = a.x + b.x; r.y = a.y + b.y; r.z = a.z + b.z; r.w = a.w + b.w;
    ((float4*)out)[i] = r;
}

// ===========================================================================
typedef CUresult (*tmap_encode_fn)(
    CUtensorMap*, CUtensorMapDataType, cuuint32_t, void*,
    const cuuint64_t*, const cuuint64_t*, const cuuint32_t*, const cuuint32_t*,
    CUtensorMapInterleave, CUtensorMapSwizzle, CUtensorMapL2promotion,
    CUtensorMapFloatOOBfill);

static void encode_fp16_3d(tmap_encode_fn enc, CUtensorMap* m, void* base,
                           cuuint64_t d0, cuuint64_t d1, cuuint64_t d2,
                           cuuint32_t b0, cuuint32_t b1) {
    cuuint64_t dims[3] = {d0, d1, d2};
    cuuint64_t strides[2] = {d0 * 2, d0 * d1 * 2};
    cuuint32_t box[3] = {b0, b1, 1};
    cuuint32_t es[3] = {1, 1, 1};
    enc(m, CU_TENSOR_MAP_DATA_TYPE_FLOAT16, 3, base, dims, strides, box, es,
        CU_TENSOR_MAP_INTERLEAVE_NONE, CU_TENSOR_MAP_SWIZZLE_128B,
        CU_TENSOR_MAP_L2_PROMOTION_L2_128B, CU_TENSOR_MAP_FLOAT_OOB_FILL_NONE);
}

extern "C" void kernel_launch(void* const* d_in, const int* in_sizes, int n_in,
                              void* d_out, int out_size) {
    const float* x  = (const float*)d_in[0];
    const float* Wr = (const float*)d_in[1];
    const float* Wi = (const float*)d_in[2];
    const float* Wo = (const float*)d_in[3];
    float* out = (float*)d_out;
    (void)in_sizes; (void)n_in; (void)out_size;

    void* fnp = nullptr;
    cudaDriverEntryPointQueryResult qr;
    cudaGetDriverEntryPoint("cuTensorMapEncodeTiled", &fnp, cudaEnableDefault, &qr);
    if (fnp) {
        tmap_encode_fn enc = (tmap_encode_fn)fnp;
        void *xs_p = nullptr, *hs_p = nullptr, *wt_p = nullptr;
        cudaGetSymbolAddress(&xs_p, g_xs);
        cudaGetSymbolAddress(&hs_p, g_hs);
        cudaGetSymbolAddress(&wt_p, g_wt16);
        static CUtensorMap hA1, hA2, hB;
        encode_fp16_3d(enc, &hA1, xs_p, 1024, ECAP, NEXP, KC, TM);
        encode_fp16_3d(enc, &hA2, hs_p, 1024, ECAP, NEXP, KC, TM);
        encode_fp16_3d(enc, &hB,  wt_p, 1024, 1024, 16,  KC, TN);
        cudaMemcpyToSymbolAsync(g_tmA1, &hA1, sizeof(CUtensorMap), 0, cudaMemcpyHostToDevice, 0);
        cudaMemcpyToSymbolAsync(g_tmA2, &hA2, sizeof(CUtensorMap), 0, cudaMemcpyHostToDevice, 0);
        cudaMemcpyToSymbolAsync(g_tmB,  &hB,  sizeof(CUtensorMap), 0, cudaMemcpyHostToDevice, 0);
    }

    cudaFuncSetAttribute(moe_tc_gemm<1>, cudaFuncAttributeMaxDynamicSharedMemorySize, SMEM_TOTAL);
    cudaFuncSetAttribute(moe_tc_gemm<2>, cudaFuncAttributeMaxDynamicSharedMemorySize, SMEM_TOTAL);

    init_kernel<<<1, 32>>>();
    router_kernel<<<T_TOK / 8, 256>>>(x, Wr);
    transpose_half_kernel<<<dim3(32, 32, 16), dim3(32, 8)>>>(Wi, Wo);
    gather_x_kernel<<<dim3(ECAP, NEXP), 128>>>(x);

    dim3 g(1024 / TN, ECAP / TM, NEXP);   // (4, 64, 8)
    moe_tc_gemm<1><<<g, 192, SMEM_TOTAL>>>();
    moe_fb_gemm<1><<<g, 256>>>();
    moe_tc_gemm<2><<<g, 192, SMEM_TOTAL>>>();
    moe_fb_gemm<2><<<g, 256>>>();

    combine_kernel<<<(T_TOK * 1024 / 4) / 256, 256>>>(out);
}

// round 5
// speedup vs baseline: 2.7643x; 1.0935x over previous
#include <cuda_runtime.h>
#include <cuda.h>
#include <cuda_fp16.h>
#include <cstdint>

// ===========================================================================
#if defined(__CUDA_ARCH_FEAT_SM100_ALL) || defined(__CUDA_ARCH_FEAT_SM103_ALL)
#define HAS_TC 1
#else
#define HAS_TC 0
#endif

#define T_TOK 8192
#define NEXP  8
#define NSLOT (T_TOK*2)
#define CAP   NSLOT
#define ECAP  8192

// tcgen05 tiling: fp16, chunk = 64 halves = 128B row; TM=256 via 2 MMAs
#define NST   3
#define KC    64
#define NCHUNK 16
#define TM    256
#define TN    256
#define A_TILE_B (TM*128)    // 32 KB
#define B_TILE_B (TN*128)    // 32 KB
#define SM_TMEM  0
#define SM_FULL  64
#define SM_EMPTY 128
#define SM_DONE  192
#define SM_A     1024
#define SM_B     (SM_A + NST*A_TILE_B)          // 99328
#define SMEM_TOTAL (SM_B + NST*B_TILE_B)        // 197632

// idesc per MMA half: M=128, N=256, fp16 in / fp32 acc
#define IDESC ((1u<<4)|((unsigned)(TN/8)<<17)|((unsigned)(128/16)<<24))

// ===========================================================================
__device__ __half g_xs[(size_t)NEXP * ECAP * 1024];
__device__ __half g_hs[(size_t)NEXP * ECAP * 1024];
__device__ __half g_wt16[(size_t)16 * 1024 * 1024];
__device__ float  g_gates[NSLOT];
__device__ int    g_lists[NEXP * CAP];
__device__ int    g_counts[NEXP];
__device__ int    g_tc_done;
__device__ __align__(128) CUtensorMap g_tmA1;
__device__ __align__(128) CUtensorMap g_tmA2;
__device__ __align__(128) CUtensorMap g_tmB;

// ===========================================================================
__device__ __forceinline__ uint32_t smem_u32(const void* p) {
    uint32_t a;
    asm("{ .reg .u64 t; cvta.to.shared.u64 t, %1; cvt.u32.u64 %0, t; }" : "=r"(a) : "l"(p));
    return a;
}
__device__ __forceinline__ uint32_t elect_one_pred() {
    uint32_t p;
    asm volatile("{\n\t.reg .pred p;\n\telect.sync _|p, 0xFFFFFFFF;\n\t"
                 "selp.b32 %0, 1, 0, p;\n\t}" : "=r"(p));
    return p;
}
#define MBARRIER_INIT(addr, cnt) \
    asm volatile("mbarrier.init.shared.b64 [%0], %1;" :: "r"((uint32_t)(addr)), "r"((uint32_t)(cnt)) : "memory")
#define MBARRIER_EXPECT_TX(addr, tx) \
    asm volatile("mbarrier.arrive.expect_tx.shared.b64 _, [%0], %1;" :: "r"((uint32_t)(addr)), "r"((uint32_t)(tx)) : "memory")
#define MBARRIER_WAIT_PARITY(addr, parity) do { \
    uint32_t _m = (uint32_t)(addr); uint32_t _p = (uint32_t)(parity); uint32_t _d; \
    asm volatile("{\n\t.reg .pred p;\n\t" \
        "mbarrier.try_wait.parity.acquire.cta.shared::cta.b64 p, [%1], %2;\n\t" \
        "selp.b32 %0, 1, 0, p;\n\t}" : "=r"(_d) : "r"(_m), "r"(_p) : "memory"); \
    if (!_d) { \
        asm volatile("{\n\t.reg .pred P1;\n\t" \
            "WL_%=:\n\t" \
            "mbarrier.try_wait.parity.acquire.cta.shared::cta.b64 P1, [%0], %1, 0x989680;\n\t" \
            "@P1 bra.uni WD_%=;\n\t" \
            "bra.uni WL_%=;\n\t" \
            "WD_%=:\n\t}" :: "r"(_m), "r"(_p) : "memory"); \
    } \
} while (0)

__device__ __forceinline__ uint32_t pack2(float a, float b) {
    __half2 h = __floats2half2_rn(a, b);
    return *reinterpret_cast<uint32_t*>(&h);
}
__device__ __forceinline__ void mma_f16(float* c, const uint32_t* a, const uint32_t* b) {
    asm volatile(
        "mma.sync.aligned.m16n8k16.row.col.f32.f16.f16.f32 "
        "{%0,%1,%2,%3}, {%4,%5,%6,%7}, {%8,%9}, {%0,%1,%2,%3};\n"
        : "+f"(c[0]), "+f"(c[1]), "+f"(c[2]), "+f"(c[3])
        : "r"(a[0]), "r"(a[1]), "r"(a[2]), "r"(a[3]), "r"(b[0]), "r"(b[1]));
}

static constexpr uint64_t SMEM_DESC_BASE_SW128 =
    (uint64_t(2) << 61) | (uint64_t(1) << 46) | (uint64_t(64) << 32) | (uint64_t(1) << 16);
#define MAKE_SMEM_DESC(a) (SMEM_DESC_BASE_SW128 | ((uint64_t)((a) >> 4) & 0x3FFF))

// ===========================================================================
__global__ void init_kernel() {
    if (threadIdx.x < NEXP) g_counts[threadIdx.x] = 0;
#if HAS_TC
    if (threadIdx.x == 0) g_tc_done = 1;
#else
    if (threadIdx.x == 0) g_tc_done = 0;
#endif
}

// Router (validated R1)
__global__ void router_kernel(const float* __restrict__ x,
                              const float* __restrict__ Wr) {
    __shared__ float sWr[NEXP][1024];
    int tid = threadIdx.x;
    for (int i = tid; i < 1024 * NEXP; i += blockDim.x) {
        int d = i >> 3, e = i & 7;
        sWr[e][d] = Wr[i];
    }
    __syncthreads();
    int warp = tid >> 5, lane = tid & 31;
    int token = blockIdx.x * 8 + warp;
    if (token >= T_TOK) return;
    const float* xr = x + (size_t)token * 1024;
    float acc[NEXP];
#pragma unroll
    for (int e = 0; e < NEXP; e++) acc[e] = 0.f;
    for (int i = lane; i < 1024; i += 32) {
        float xv = xr[i];
#pragma unroll
        for (int e = 0; e < NEXP; e++) acc[e] += xv * sWr[e][i];
    }
#pragma unroll
    for (int e = 0; e < NEXP; e++)
#pragma unroll
        for (int off = 16; off > 0; off >>= 1)
            acc[e] += __shfl_xor_sync(0xffffffffu, acc[e], off);
    if (lane == 0) {
        float mx = acc[0];
#pragma unroll
        for (int e = 1; e < NEXP; e++) mx = fmaxf(mx, acc[e]);
        float p[NEXP], s = 0.f;
#pragma unroll
        for (int e = 0; e < NEXP; e++) { p[e] = expf(acc[e] - mx); s += p[e]; }
        float inv = 1.f / s;
#pragma unroll
        for (int e = 0; e < NEXP; e++) p[e] *= inv;
        int i0 = 0; float b0 = p[0];
#pragma unroll
        for (int e = 1; e < NEXP; e++) if (p[e] > b0) { b0 = p[e]; i0 = e; }
        int i1 = -1; float b1 = -1.f;
#pragma unroll
        for (int e = 0; e < NEXP; e++)
            if (e != i0 && p[e] > b1) { b1 = p[e]; i1 = e; }
        int s0 = token * 2, s1 = token * 2 + 1;
        g_gates[s0] = b0;
        g_gates[s1] = b1;
        int pos0 = atomicAdd(&g_counts[i0], 1);
        g_lists[i0 * CAP + pos0] = s0;
        int pos1 = atomicAdd(&g_counts[i1], 1);
        g_lists[i1 * CAP + pos1] = s1;
    }
}

// Weights: [e][k][n] fp32 -> [mat*8+e][n][k] fp16
__global__ void transpose_half_kernel(const float* __restrict__ Wi,
                                      const float* __restrict__ Wo) {
    __shared__ float t[32][33];
    int mat = blockIdx.z >> 3, e = blockIdx.z & 7;
    const float* src = (mat ? Wo : Wi) + (size_t)e * 1024 * 1024;
    __half* dst = g_wt16 + (size_t)blockIdx.z * 1024 * 1024;
    int k0 = blockIdx.y * 32, n0 = blockIdx.x * 32;
    int tx = threadIdx.x, ty = threadIdx.y;
#pragma unroll
    for (int i = 0; i < 4; i++)
        t[ty + 8 * i][tx] = src[(size_t)(k0 + ty + 8 * i) * 1024 + n0 + tx];
    __syncthreads();
#pragma unroll
    for (int i = 0; i < 4; i++) {
        int n = ty + 8 * i;
        dst[(size_t)(n0 + n) * 1024 + k0 + tx] = __float2half_rn(t[tx][n]);
    }
}

// Gather: 16 rows/block, 16 threads/row, 256B read + 128B write per thread
__global__ __launch_bounds__(256)
void gather_x_kernel(const float* __restrict__ x) {
    int e = blockIdx.y;
    int cnt = g_counts[e];
    int row0 = blockIdx.x * 16;
    if (row0 >= cnt) return;
    int tid = threadIdx.x;
    int pos = row0 + (tid >> 4);
    int seg = tid & 15;                   // 64 floats per seg
    if (pos >= cnt) return;
    int token = g_lists[e * CAP + pos] >> 1;
    const float4* src = (const float4*)(x + (size_t)token * 1024 + seg * 64);
    uint4* dst = (uint4*)(g_xs + ((size_t)(e * ECAP + pos)) * 1024 + seg * 64);
#pragma unroll
    for (int j = 0; j < 8; j++) {
        float4 a = src[2 * j], b = src[2 * j + 1];
        uint4 w;
        w.x = pack2(a.x, a.y); w.y = pack2(a.z, a.w);
        w.z = pack2(b.x, b.y); w.w = pack2(b.z, b.w);
        dst[j] = w;
    }
}

// ===========================================================================
// Pure-TMA tcgen05 fp16 grouped GEMM, TM=256 (two M=128 MMAs, full TMEM).
// STAGE 1: A=g_xs -> g_hs fp16.  STAGE 2: A=g_hs -> red.add into out.
template <int STAGE>
__global__ __launch_bounds__(192, 1)
void moe_tc_gemm(float* __restrict__ out) {
#if HAS_TC
    extern __shared__ char smem[];
    const int e = blockIdx.z;
    const int cnt = g_counts[e];
    const int m0 = blockIdx.y * TM;
    if (m0 >= cnt) return;
    const int n0 = blockIdx.x * TN;
    const uint32_t sb = smem_u32(smem);
    const int tid = threadIdx.x, wid = tid >> 5;

    if (tid == 0) {
#pragma unroll
        for (int s = 0; s < NST; s++) {
            MBARRIER_INIT(sb + SM_FULL + 8 * s, 1);
            MBARRIER_INIT(sb + SM_EMPTY + 8 * s, 1);
        }
        MBARRIER_INIT(sb + SM_DONE, 1);
    }
    if (wid == 5)
        asm volatile("tcgen05.alloc.cta_group::1.sync.aligned.shared::cta.b32 [%0], %1;"
                     :: "r"(sb + SM_TMEM), "r"(512u) : "memory");
    __syncthreads();
    uint32_t tmem;
    asm volatile("ld.shared.b32 %0, [%1];" : "=r"(tmem) : "r"(sb + SM_TMEM));

    if (wid == 4) {
        // ---- TMA producer: A (32KB) + B (32KB) per chunk ----
        if (elect_one_pred()) {
            const CUtensorMap* tmA = (STAGE == 1) ? &g_tmA1 : &g_tmA2;
            const CUtensorMap* tmB = &g_tmB;
            int zb = (STAGE == 1) ? e : NEXP + e;
            int s = 0, ph = 1;
            for (int c = 0; c < NCHUNK; c++) {
                MBARRIER_WAIT_PARITY(sb + SM_EMPTY + 8 * s, ph);
                MBARRIER_EXPECT_TX(sb + SM_FULL + 8 * s, A_TILE_B + B_TILE_B);
                asm volatile("cp.async.bulk.tensor.3d.shared::cta.global.tile.mbarrier::complete_tx::bytes "
                    "[%0], [%1, {%2, %3, %4}], [%5];"
                    :: "r"(sb + SM_A + s * A_TILE_B), "l"(tmA),
                       "r"(c * KC), "r"(m0), "r"(e),
                       "r"(sb + SM_FULL + 8 * s) : "memory");
                asm volatile("cp.async.bulk.tensor.3d.shared::cta.global.tile.mbarrier::complete_tx::bytes "
                    "[%0], [%1, {%2, %3, %4}], [%5];"
                    :: "r"(sb + SM_B + s * B_TILE_B), "l"(tmB),
                       "r"(c * KC), "r"(n0), "r"(zb),
                       "r"(sb + SM_FULL + 8 * s) : "memory");
                if (++s == NST) { s = 0; ph ^= 1; }
            }
        }
    } else if (wid == 5) {
        // ---- MMA warp: 2 halves x 4 K-subs per chunk ----
        if (elect_one_pred()) {
            int s = 0, ph = 0;
            for (int c = 0; c < NCHUNK; c++) {
                MBARRIER_WAIT_PARITY(sb + SM_FULL + 8 * s, ph);
                uint64_t ad0 = MAKE_SMEM_DESC(sb + SM_A + s * A_TILE_B);
                uint64_t ad1 = MAKE_SMEM_DESC(sb + SM_A + s * A_TILE_B + A_TILE_B / 2);
                uint64_t bd  = MAKE_SMEM_DESC(sb + SM_B + s * B_TILE_B);
#pragma unroll
                for (int sub = 0; sub < 4; sub++) {
                    uint32_t en = (unsigned)((c | sub) != 0);
                    asm volatile("{\n\t.reg .pred p;\n\tsetp.ne.u32 p, %6, 0;\n\t"
                        "tcgen05.mma.cta_group::1.kind::f16 [%0], %1, %2, %3, "
                        "{%4, %4, %4, %4}, p;\n\t}"
                        :: "r"(tmem), "l"(ad0 + 2 * sub), "l"(bd + 2 * sub),
                           "r"(IDESC), "r"(0u), "r"(0u), "r"(en) : "memory");
                    asm volatile("{\n\t.reg .pred p;\n\tsetp.ne.u32 p, %6, 0;\n\t"
                        "tcgen05.mma.cta_group::1.kind::f16 [%0], %1, %2, %3, "
                        "{%4, %4, %4, %4}, p;\n\t}"
                        :: "r"(tmem + 256), "l"(ad1 + 2 * sub), "l"(bd + 2 * sub),
                           "r"(IDESC), "r"(0u), "r"(0u), "r"(en) : "memory");
                }
                asm volatile("tcgen05.commit.cta_group::1.mbarrier::arrive::one.shared::cluster.b64 [%0];"
                             :: "r"(sb + SM_EMPTY + 8 * s) : "memory");
                if (++s == NST) { s = 0; ph ^= 1; }
            }
            asm volatile("tcgen05.commit.cta_group::1.mbarrier::arrive::one.shared::cluster.b64 [%0];"
                         :: "r"(sb + SM_DONE) : "memory");
        }
    }

    if (wid < 4) {
        // ---- Epilogue: 128 threads; thread handles rows m0+tid and m0+128+tid ----
        MBARRIER_WAIT_PARITY(sb + SM_DONE, 0);
        asm volatile("tcgen05.fence::after_thread_sync;" ::: "memory");
        const int* lst = g_lists + e * CAP + m0;
#pragma unroll
        for (int half = 0; half < 2; half++) {
            int rr = half * 128 + tid;
            bool val = (m0 + rr) < cnt;
            uint32_t tbase = tmem + half * 256;
            int slot = (STAGE == 2 && val) ? lst[rr] : 0;
            float gate = (STAGE == 2) ? (val ? g_gates[slot] : 0.f) : 1.f;
            float* orow = out + (size_t)(slot >> 1) * 1024 + n0;
            __half* hrow = g_hs + ((size_t)(e * ECAP + m0 + rr)) * 1024 + n0;
#pragma unroll
            for (int cb = 0; cb < 8; cb++) {
                uint32_t regs[32];
                asm volatile("tcgen05.ld.sync.aligned.32x32b.x32.b32 "
                    "{%0,%1,%2,%3,%4,%5,%6,%7,%8,%9,%10,%11,%12,%13,%14,%15,"
                    "%16,%17,%18,%19,%20,%21,%22,%23,%24,%25,%26,%27,%28,%29,%30,%31}, [%32];"
                    : "=r"(regs[0]),"=r"(regs[1]),"=r"(regs[2]),"=r"(regs[3]),
                      "=r"(regs[4]),"=r"(regs[5]),"=r"(regs[6]),"=r"(regs[7]),
                      "=r"(regs[8]),"=r"(regs[9]),"=r"(regs[10]),"=r"(regs[11]),
                      "=r"(regs[12]),"=r"(regs[13]),"=r"(regs[14]),"=r"(regs[15]),
                      "=r"(regs[16]),"=r"(regs[17]),"=r"(regs[18]),"=r"(regs[19]),
                      "=r"(regs[20]),"=r"(regs[21]),"=r"(regs[22]),"=r"(regs[23]),
                      "=r"(regs[24]),"=r"(regs[25]),"=r"(regs[26]),"=r"(regs[27]),
                      "=r"(regs[28]),"=r"(regs[29]),"=r"(regs[30]),"=r"(regs[31])
                    : "r"(tbase + cb * 32));
                asm volatile("tcgen05.wait::ld.sync.aligned;" ::: "memory");
                if (val) {
                    if (STAGE == 1) {
#pragma unroll
                        for (int q = 0; q < 4; q++) {
                            uint4 w;
                            w.x = pack2(__uint_as_float(regs[q*8+0]), __uint_as_float(regs[q*8+1]));
                            w.y = pack2(__uint_as_float(regs[q*8+2]), __uint_as_float(regs[q*8+3]));
                            w.z = pack2(__uint_as_float(regs[q*8+4]), __uint_as_float(regs[q*8+5]));
                            w.w = pack2(__uint_as_float(regs[q*8+6]), __uint_as_float(regs[q*8+7]));
                            *(uint4*)(hrow + cb * 32 + q * 8) = w;
                        }
                    } else {
#pragma unroll
                        for (int q = 0; q < 8; q++) {
                            float v0 = __uint_as_float(regs[q * 4 + 0]) * gate;
                            float v1 = __uint_as_float(regs[q * 4 + 1]) * gate;
                            float v2 = __uint_as_float(regs[q * 4 + 2]) * gate;
                            float v3 = __uint_as_float(regs[q * 4 + 3]) * gate;
                            asm volatile("red.global.add.v4.f32 [%0], {%1, %2, %3, %4};"
                                :: "l"(orow + cb * 32 + q * 4),
                                   "f"(v0), "f"(v1), "f"(v2), "f"(v3) : "memory");
                        }
                    }
                }
            }
        }
    }

    __syncthreads();
    if (wid == 5) {
        asm volatile("tcgen05.relinquish_alloc_permit.cta_group::1.sync.aligned;");
        asm volatile("tcgen05.dealloc.cta_group::1.sync.aligned.b32 %0, %1;" :: "r"(tmem), "r"(512u));
    }
#endif
}

// ===========================================================================
// Fallback fp16 mma.sync GEMM (skipped when tcgen05 path ran).
template <int STAGE>
__global__ __launch_bounds__(256, 1)
void moe_fb_gemm(float* __restrict__ out) {
    if (g_tc_done) return;
    const int e = blockIdx.z;
    const int cnt = g_counts[e];
    const int m0 = blockIdx.y * 128;
    if (m0 >= cnt) return;
    const int n0 = blockIdx.x * 256;

    const __half* Asrc = ((STAGE == 1) ? g_xs : g_hs) + (size_t)e * ECAP * 1024;
    const __half* B = g_wt16 + (size_t)((STAGE == 1 ? 0 : 8) + e) * 1024 * 1024;
    const int* lst = g_lists + e * CAP + m0;

    __shared__ uint32_t sA32[128 * 20];
    __shared__ uint32_t sB32[256 * 20];

    const int tid = threadIdx.x;
    const int arow = tid >> 3, aseg = tid & 7;
    const __half* aptr[4];
#pragma unroll
    for (int p = 0; p < 4; p++) {
        int r = arow + 32 * p;
        aptr[p] = (m0 + r < cnt) ? Asrc + (size_t)(m0 + r) * 1024 + aseg * 4 : nullptr;
    }
    const int brow = tid >> 2, bseg = tid & 3;
    const __half* brp[4];
#pragma unroll
    for (int p = 0; p < 4; p++)
        brp[p] = B + (size_t)(n0 + brow + 64 * p) * 1024 + bseg * 8;

    const int warp = tid >> 5, lane = tid & 31;
    const int wm = warp & 1, wn = warp >> 1;
    const int g = lane >> 2, tg = lane & 3;

    float c[4][8][4];
#pragma unroll
    for (int i = 0; i < 4; i++)
#pragma unroll
        for (int j = 0; j < 8; j++)
#pragma unroll
            for (int q = 0; q < 4; q++) c[i][j][q] = 0.f;

    uint2 aReg[4];
    uint4 bReg[4];
#pragma unroll
    for (int p = 0; p < 4; p++)
        aReg[p] = aptr[p] ? *(const uint2*)(aptr[p]) : make_uint2(0, 0);
#pragma unroll
    for (int p = 0; p < 4; p++)
        bReg[p] = *(const uint4*)(brp[p]);

    for (int kt = 0; kt < 32; kt++) {
        if (kt) __syncthreads();
#pragma unroll
        for (int p = 0; p < 4; p++)
            *(uint2*)&sA32[(arow + 32 * p) * 20 + 2 * aseg] = aReg[p];
#pragma unroll
        for (int p = 0; p < 4; p++)
            *(uint4*)&sB32[(brow + 64 * p) * 20 + 4 * bseg] = bReg[p];
        __syncthreads();

        if (kt < 31) {
            int ko = (kt + 1) * 32;
#pragma unroll
            for (int p = 0; p < 4; p++)
                aReg[p] = aptr[p] ? *(const uint2*)(aptr[p] + ko) : make_uint2(0, 0);
#pragma unroll
            for (int p = 0; p < 4; p++)
                bReg[p] = *(const uint4*)(brp[p] + ko);
        }

#pragma unroll
        for (int ks = 0; ks < 2; ks++) {
            const int kp = 8 * ks;
            uint32_t a[4][4], b[8][2];
#pragma unroll
            for (int mf = 0; mf < 4; mf++) {
                int row = wm * 64 + mf * 16 + g;
                a[mf][0] = sA32[row * 20 + kp + tg];
                a[mf][1] = sA32[(row + 8) * 20 + kp + tg];
                a[mf][2] = sA32[row * 20 + kp + tg + 4];
                a[mf][3] = sA32[(row + 8) * 20 + kp + tg + 4];
            }
#pragma unroll
            for (int nf = 0; nf < 8; nf++) {
                int n = wn * 64 + nf * 8 + g;
                b[nf][0] = sB32[n * 20 + kp + tg];
                b[nf][1] = sB32[n * 20 + kp + tg + 4];
            }
#pragma unroll
            for (int mf = 0; mf < 4; mf++)
#pragma unroll
                for (int nf = 0; nf < 8; nf++)
                    mma_f16(c[mf][nf], a[mf], b[nf]);
        }
    }

#pragma unroll
    for (int mf = 0; mf < 4; mf++) {
#pragma unroll
        for (int half = 0; half < 2; half++) {
            int r = wm * 64 + mf * 16 + g + half * 8;
            if (m0 + r >= cnt) continue;
            if (STAGE == 1) {
                __half* hrow = g_hs + ((size_t)(e * ECAP + m0 + r)) * 1024 + n0;
#pragma unroll
                for (int nf = 0; nf < 8; nf++) {
                    int cc = wn * 64 + nf * 8 + tg * 2;
                    *(uint32_t*)(hrow + cc) =
                        pack2(c[mf][nf][half * 2 + 0], c[mf][nf][half * 2 + 1]);
                }
            } else {
                int slot = lst[r];
                float gate = g_gates[slot];
                float* orow = out + (size_t)(slot >> 1) * 1024 + n0;
#pragma unroll
                for (int nf = 0; nf < 8; nf++) {
                    int cc = wn * 64 + nf * 8 + tg * 2;
                    atomicAdd(&orow[cc], c[mf][nf][half * 2 + 0] * gate);
                    atomicAdd(&orow[cc + 1], c[mf][nf][half * 2 + 1] * gate);
                }
            }
        }
    }
}

// ===========================================================================
typedef CUresult (*tmap_encode_fn)(
    CUtensorMap*, CUtensorMapDataType, cuuint32_t, void*,
    const cuuint64_t*, const cuuint64_t*, const cuuint32_t*, const cuuint32_t*,
    CUtensorMapInterleave, CUtensorMapSwizzle, CUtensorMapL2promotion,
    CUtensorMapFloatOOBfill);

static void encode_fp16_3d(tmap_encode_fn enc, CUtensorMap* m, void* base,
                           cuuint64_t d0, cuuint64_t d1, cuuint64_t d2,
                           cuuint32_t b0, cuuint32_t b1) {
    cuuint64_t dims[3] = {d0, d1, d2};
    cuuint64_t strides[2] = {d0 * 2, d0 * d1 * 2};
    cuuint32_t box[3] = {b0, b1, 1};
    cuuint32_t es[3] = {1, 1, 1};
    enc(m, CU_TENSOR_MAP_DATA_TYPE_FLOAT16, 3, base, dims, strides, box, es,
        CU_TENSOR_MAP_INTERLEAVE_NONE, CU_TENSOR_MAP_SWIZZLE_128B,
        CU_TENSOR_MAP_L2_PROMOTION_L2_128B, CU_TENSOR_MAP_FLOAT_OOB_FILL_NONE);
}

extern "C" void kernel_launch(void* const* d_in, const int* in_sizes, int n_in,
                              void* d_out, int out_size) {
    const float* x  = (const float*)d_in[0];
    const float* Wr = (const float*)d_in[1];
    const float* Wi = (const float*)d_in[2];
    const float* Wo = (const float*)d_in[3];
    float* out = (float*)d_out;
    (void)in_sizes; (void)n_in; (void)out_size;

    void* fnp = nullptr;
    cudaDriverEntryPointQueryResult qr;
    cudaGetDriverEntryPoint("cuTensorMapEncodeTiled", &fnp, cudaEnableDefault, &qr);
    if (fnp) {
        tmap_encode_fn enc = (tmap_encode_fn)fnp;
        void *xs_p = nullptr, *hs_p = nullptr, *wt_p = nullptr;
        cudaGetSymbolAddress(&xs_p, g_xs);
        cudaGetSymbolAddress(&hs_p, g_hs);
        cudaGetSymbolAddress(&wt_p, g_wt16);
        static CUtensorMap hA1, hA2, hB;
        encode_fp16_3d(enc, &hA1, xs_p, 1024, ECAP, NEXP, KC, TM);
        encode_fp16_3d(enc, &hA2, hs_p, 1024, ECAP, NEXP, KC, TM);
        encode_fp16_3d(enc, &hB,  wt_p, 1024, 1024, 16,  KC, TN);
        cudaMemcpyToSymbolAsync(g_tmA1, &hA1, sizeof(CUtensorMap), 0, cudaMemcpyHostToDevice, 0);
        cudaMemcpyToSymbolAsync(g_tmA2, &hA2, sizeof(CUtensorMap), 0, cudaMemcpyHostToDevice, 0);
        cudaMemcpyToSymbolAsync(g_tmB,  &hB,  sizeof(CUtensorMap), 0, cudaMemcpyHostToDevice, 0);
    }

    cudaFuncSetAttribute(moe_tc_gemm<1>, cudaFuncAttributeMaxDynamicSharedMemorySize, SMEM_TOTAL);
    cudaFuncSetAttribute(moe_tc_gemm<2>, cudaFuncAttributeMaxDynamicSharedMemorySize, SMEM_TOTAL);

    init_kernel<<<1, 32>>>();
    cudaMemsetAsync(d_out, 0, (size_t)T_TOK * 1024 * sizeof(float), 0);
    router_kernel<<<T_TOK / 8, 256>>>(x, Wr);
    transpose_half_kernel<<<dim3(32, 32, 16), dim3(32, 8)>>>(Wi, Wo);
    gather_x_kernel<<<dim3(ECAP / 16, NEXP), 256>>>(x);

    dim3 gtc(1024 / TN, ECAP / TM, NEXP);    // (4, 32, 8)
    dim3 gfb(1024 / 256, ECAP / 128, NEXP);  // (4, 64, 8)
    moe_tc_gemm<1><<<gtc, 192, SMEM_TOTAL>>>(out);
    moe_fb_gemm<1><<<gfb, 256>>>(out);
    moe_tc_gemm<2><<<gtc, 192, SMEM_TOTAL>>>(out);
    moe_fb_gemm<2><<<gfb, 256>>>(out);
}

// round 7
// speedup vs baseline: 3.0692x; 1.1103x over previous
#include <cuda_runtime.h>
#include <cuda.h>
#include <cuda_fp16.h>
#include <cstdint>

// ===========================================================================
#if defined(__CUDA_ARCH_FEAT_SM100_ALL) || defined(__CUDA_ARCH_FEAT_SM103_ALL)
#define HAS_TC 1
#else
#define HAS_TC 0
#endif

#define T_TOK 8192
#define NEXP  8
#define NSLOT (T_TOK*2)
#define CAP   NSLOT
#define ECAP  8192

// tcgen05 tiling: fp16, chunk = 64 halves = 128B row; TM=256 via 2 MMAs
#define NST   3
#define KC    64
#define NCHUNK 16
#define TM    256
#define TN    256
#define A_TILE_B (TM*128)    // 32 KB
#define B_TILE_B (TN*128)    // 32 KB
#define SM_TMEM  0
#define SM_FULL  64
#define SM_EMPTY 128
#define SM_DONE  192
#define SM_A     1024
#define SM_B     (SM_A + NST*A_TILE_B)
#define SMEM_TOTAL (SM_B + NST*B_TILE_B)   // 197632

#define IDESC ((1u<<4)|((unsigned)(TN/8)<<17)|((unsigned)(128/16)<<24))

// ===========================================================================
__device__ __half g_xs[(size_t)NEXP * ECAP * 1024];
__device__ __half g_hs[(size_t)NEXP * ECAP * 1024];
__device__ __half g_wt16[(size_t)16 * 1024 * 1024];
__device__ float  g_gates[NSLOT];
__device__ int    g_lists[NEXP * CAP];
__device__ int    g_counts[NEXP];
__device__ int    g_tc_done;
__device__ __align__(128) CUtensorMap g_tmA1;
__device__ __align__(128) CUtensorMap g_tmA2;
__device__ __align__(128) CUtensorMap g_tmB;

// ===========================================================================
__device__ __forceinline__ uint32_t smem_u32(const void* p) {
    uint32_t a;
    asm("{ .reg .u64 t; cvta.to.shared.u64 t, %1; cvt.u32.u64 %0, t; }" : "=r"(a) : "l"(p));
    return a;
}
__device__ __forceinline__ uint32_t elect_one_pred() {
    uint32_t p;
    asm volatile("{\n\t.reg .pred p;\n\telect.sync _|p, 0xFFFFFFFF;\n\t"
                 "selp.b32 %0, 1, 0, p;\n\t}" : "=r"(p));
    return p;
}
#define MBARRIER_INIT(addr, cnt) \
    asm volatile("mbarrier.init.shared.b64 [%0], %1;" :: "r"((uint32_t)(addr)), "r"((uint32_t)(cnt)) : "memory")
#define MBARRIER_EXPECT_TX(addr, tx) \
    asm volatile("mbarrier.arrive.expect_tx.shared.b64 _, [%0], %1;" :: "r"((uint32_t)(addr)), "r"((uint32_t)(tx)) : "memory")
#define MBARRIER_WAIT_PARITY(addr, parity) do { \
    uint32_t _m = (uint32_t)(addr); uint32_t _p = (uint32_t)(parity); uint32_t _d; \
    asm volatile("{\n\t.reg .pred p;\n\t" \
        "mbarrier.try_wait.parity.acquire.cta.shared::cta.b64 p, [%1], %2;\n\t" \
        "selp.b32 %0, 1, 0, p;\n\t}" : "=r"(_d) : "r"(_m), "r"(_p) : "memory"); \
    if (!_d) { \
        asm volatile("{\n\t.reg .pred P1;\n\t" \
            "WL_%=:\n\t" \
            "mbarrier.try_wait.parity.acquire.cta.shared::cta.b64 P1, [%0], %1, 0x989680;\n\t" \
            "@P1 bra.uni WD_%=;\n\t" \
            "bra.uni WL_%=;\n\t" \
            "WD_%=:\n\t}" :: "r"(_m), "r"(_p) : "memory"); \
    } \
} while (0)

__device__ __forceinline__ uint32_t pack2(float a, float b) {
    __half2 h = __floats2half2_rn(a, b);
    return *reinterpret_cast<uint32_t*>(&h);
}
__device__ __forceinline__ void mma_f16(float* c, const uint32_t* a, const uint32_t* b) {
    asm volatile(
        "mma.sync.aligned.m16n8k16.row.col.f32.f16.f16.f32 "
        "{%0,%1,%2,%3}, {%4,%5,%6,%7}, {%8,%9}, {%0,%1,%2,%3};\n"
        : "+f"(c[0]), "+f"(c[1]), "+f"(c[2]), "+f"(c[3])
        : "r"(a[0]), "r"(a[1]), "r"(a[2]), "r"(a[3]), "r"(b[0]), "r"(b[1]));
}

static constexpr uint64_t SMEM_DESC_BASE_SW128 =
    (uint64_t(2) << 61) | (uint64_t(1) << 46) | (uint64_t(64) << 32) | (uint64_t(1) << 16);
#define MAKE_SMEM_DESC(a) (SMEM_DESC_BASE_SW128 | ((uint64_t)((a) >> 4) & 0x3FFF))

// ===========================================================================
__global__ void init_kernel() {
    if (threadIdx.x < NEXP) g_counts[threadIdx.x] = 0;
#if HAS_TC
    if (threadIdx.x == 0) g_tc_done = 1;
#else
    if (threadIdx.x == 0) g_tc_done = 0;
#endif
}

// Router (validated R1)
__global__ void router_kernel(const float* __restrict__ x,
                              const float* __restrict__ Wr) {
    __shared__ float sWr[NEXP][1024];
    int tid = threadIdx.x;
    for (int i = tid; i < 1024 * NEXP; i += blockDim.x) {
        int d = i >> 3, e = i & 7;
        sWr[e][d] = Wr[i];
    }
    __syncthreads();
    int warp = tid >> 5, lane = tid & 31;
    int token = blockIdx.x * 8 + warp;
    if (token >= T_TOK) return;
    const float* xr = x + (size_t)token * 1024;
    float acc[NEXP];
#pragma unroll
    for (int e = 0; e < NEXP; e++) acc[e] = 0.f;
    for (int i = lane; i < 1024; i += 32) {
        float xv = xr[i];
#pragma unroll
        for (int e = 0; e < NEXP; e++) acc[e] += xv * sWr[e][i];
    }
#pragma unroll
    for (int e = 0; e < NEXP; e++)
#pragma unroll
        for (int off = 16; off > 0; off >>= 1)
            acc[e] += __shfl_xor_sync(0xffffffffu, acc[e], off);
    if (lane == 0) {
        float mx = acc[0];
#pragma unroll
        for (int e = 1; e < NEXP; e++) mx = fmaxf(mx, acc[e]);
        float p[NEXP], s = 0.f;
#pragma unroll
        for (int e = 0; e < NEXP; e++) { p[e] = expf(acc[e] - mx); s += p[e]; }
        float inv = 1.f / s;
#pragma unroll
        for (int e = 0; e < NEXP; e++) p[e] *= inv;
        int i0 = 0; float b0 = p[0];
#pragma unroll
        for (int e = 1; e < NEXP; e++) if (p[e] > b0) { b0 = p[e]; i0 = e; }
        int i1 = -1; float b1 = -1.f;
#pragma unroll
        for (int e = 0; e < NEXP; e++)
            if (e != i0 && p[e] > b1) { b1 = p[e]; i1 = e; }
        int s0 = token * 2, s1 = token * 2 + 1;
        g_gates[s0] = b0;
        g_gates[s1] = b1;
        int pos0 = atomicAdd(&g_counts[i0], 1);
        g_lists[i0 * CAP + pos0] = s0;
        int pos1 = atomicAdd(&g_counts[i1], 1);
        g_lists[i1 * CAP + pos1] = s1;
    }
}

// Weights: [e][k][n] fp32 -> [mat*8+e][n][k] fp16
__global__ void transpose_half_kernel(const float* __restrict__ Wi,
                                      const float* __restrict__ Wo) {
    __shared__ float t[32][33];
    int mat = blockIdx.z >> 3, e = blockIdx.z & 7;
    const float* src = (mat ? Wo : Wi) + (size_t)e * 1024 * 1024;
    __half* dst = g_wt16 + (size_t)blockIdx.z * 1024 * 1024;
    int k0 = blockIdx.y * 32, n0 = blockIdx.x * 32;
    int tx = threadIdx.x, ty = threadIdx.y;
#pragma unroll
    for (int i = 0; i < 4; i++)
        t[ty + 8 * i][tx] = src[(size_t)(k0 + ty + 8 * i) * 1024 + n0 + tx];
    __syncthreads();
#pragma unroll
    for (int i = 0; i < 4; i++) {
        int n = ty + 8 * i;
        dst[(size_t)(n0 + n) * 1024 + k0 + tx] = __float2half_rn(t[tx][n]);
    }
}

// Coalesced gather: block handles 8 rows; 256 threads cooperate per row.
// Thread t reads float4 #t of the row (warp = 512B contiguous read),
// writes half2x2 (warp = 256B contiguous write).
__global__ __launch_bounds__(256)
void gather_x_kernel(const float* __restrict__ x) {
    int e = blockIdx.y;
    int cnt = g_counts[e];
    int row0 = blockIdx.x * 8;
    if (row0 >= cnt) return;
    int t = threadIdx.x;
    int nrows = min(8, cnt - row0);
    for (int r = 0; r < nrows; r++) {
        int token = g_lists[e * CAP + row0 + r] >> 1;
        const float4* src = (const float4*)(x + (size_t)token * 1024);
        uint2* dst = (uint2*)(g_xs + ((size_t)(e * ECAP + row0 + r)) * 1024);
        float4 v = src[t];
        uint2 w;
        w.x = pack2(v.x, v.y);
        w.y = pack2(v.z, v.w);
        dst[t] = w;
    }
}

// ===========================================================================
// Pure-TMA tcgen05 fp16 grouped GEMM, TM=256 (two M=128 MMAs, full TMEM).
// STAGE 1: A=g_xs -> g_hs fp16.  STAGE 2: A=g_hs -> red.add into out.
template <int STAGE>
__global__ __launch_bounds__(192, 1)
void moe_tc_gemm(float* __restrict__ out) {
#if HAS_TC
    extern __shared__ char smem[];
    const int e = blockIdx.z;
    const int cnt = g_counts[e];
    const int m0 = blockIdx.y * TM;
    if (m0 >= cnt) return;
    const int n0 = blockIdx.x * TN;
    const uint32_t sb = smem_u32(smem);
    const int tid = threadIdx.x, wid = tid >> 5;

    if (tid == 0) {
#pragma unroll
        for (int s = 0; s < NST; s++) {
            MBARRIER_INIT(sb + SM_FULL + 8 * s, 1);
            MBARRIER_INIT(sb + SM_EMPTY + 8 * s, 1);
        }
        MBARRIER_INIT(sb + SM_DONE, 1);
    }
    if (wid == 5)
        asm volatile("tcgen05.alloc.cta_group::1.sync.aligned.shared::cta.b32 [%0], %1;"
                     :: "r"(sb + SM_TMEM), "r"(512u) : "memory");
    __syncthreads();
    uint32_t tmem;
    asm volatile("ld.shared.b32 %0, [%1];" : "=r"(tmem) : "r"(sb + SM_TMEM));

    if (wid == 4) {
        if (elect_one_pred()) {
            const CUtensorMap* tmA = (STAGE == 1) ? &g_tmA1 : &g_tmA2;
            const CUtensorMap* tmB = &g_tmB;
            int zb = (STAGE == 1) ? e : NEXP + e;
            int s = 0, ph = 1;
            for (int c = 0; c < NCHUNK; c++) {
                MBARRIER_WAIT_PARITY(sb + SM_EMPTY + 8 * s, ph);
                MBARRIER_EXPECT_TX(sb + SM_FULL + 8 * s, A_TILE_B + B_TILE_B);
                asm volatile("cp.async.bulk.tensor.3d.shared::cta.global.tile.mbarrier::complete_tx::bytes "
                    "[%0], [%1, {%2, %3, %4}], [%5];"
                    :: "r"(sb + SM_A + s * A_TILE_B), "l"(tmA),
                       "r"(c * KC), "r"(m0), "r"(e),
                       "r"(sb + SM_FULL + 8 * s) : "memory");
                asm volatile("cp.async.bulk.tensor.3d.shared::cta.global.tile.mbarrier::complete_tx::bytes "
                    "[%0], [%1, {%2, %3, %4}], [%5];"
                    :: "r"(sb + SM_B + s * B_TILE_B), "l"(tmB),
                       "r"(c * KC), "r"(n0), "r"(zb),
                       "r"(sb + SM_FULL + 8 * s) : "memory");
                if (++s == NST) { s = 0; ph ^= 1; }
            }
        }
    } else if (wid == 5) {
        if (elect_one_pred()) {
            int s = 0, ph = 0;
            for (int c = 0; c < NCHUNK; c++) {
                MBARRIER_WAIT_PARITY(sb + SM_FULL + 8 * s, ph);
                uint64_t ad0 = MAKE_SMEM_DESC(sb + SM_A + s * A_TILE_B);
                uint64_t ad1 = MAKE_SMEM_DESC(sb + SM_A + s * A_TILE_B + A_TILE_B / 2);
                uint64_t bd  = MAKE_SMEM_DESC(sb + SM_B + s * B_TILE_B);
#pragma unroll
                for (int sub = 0; sub < 4; sub++) {
                    uint32_t en = (unsigned)((c | sub) != 0);
                    asm volatile("{\n\t.reg .pred p;\n\tsetp.ne.u32 p, %6, 0;\n\t"
                        "tcgen05.mma.cta_group::1.kind::f16 [%0], %1, %2, %3, "
                        "{%4, %4, %4, %4}, p;\n\t}"
                        :: "r"(tmem), "l"(ad0 + 2 * sub), "l"(bd + 2 * sub),
                           "r"(IDESC), "r"(0u), "r"(0u), "r"(en) : "memory");
                    asm volatile("{\n\t.reg .pred p;\n\tsetp.ne.u32 p, %6, 0;\n\t"
                        "tcgen05.mma.cta_group::1.kind::f16 [%0], %1, %2, %3, "
                        "{%4, %4, %4, %4}, p;\n\t}"
                        :: "r"(tmem + 256), "l"(ad1 + 2 * sub), "l"(bd + 2 * sub),
                           "r"(IDESC), "r"(0u), "r"(0u), "r"(en) : "memory");
                }
                asm volatile("tcgen05.commit.cta_group::1.mbarrier::arrive::one.shared::cluster.b64 [%0];"
                             :: "r"(sb + SM_EMPTY + 8 * s) : "memory");
                if (++s == NST) { s = 0; ph ^= 1; }
            }
            asm volatile("tcgen05.commit.cta_group::1.mbarrier::arrive::one.shared::cluster.b64 [%0];"
                         :: "r"(sb + SM_DONE) : "memory");
        }
    }

    if (wid < 4) {
        MBARRIER_WAIT_PARITY(sb + SM_DONE, 0);
        asm volatile("tcgen05.fence::after_thread_sync;" ::: "memory");
        const int* lst = g_lists + e * CAP + m0;
#pragma unroll
        for (int half = 0; half < 2; half++) {
            int rr = half * 128 + tid;
            bool val = (m0 + rr) < cnt;
            uint32_t tbase = tmem + half * 256;
            int slot = (STAGE == 2 && val) ? lst[rr] : 0;
            float gate = (STAGE == 2) ? (val ? g_gates[slot] : 0.f) : 1.f;
            float* orow = out + (size_t)(slot >> 1) * 1024 + n0;
            __half* hrow = g_hs + ((size_t)(e * ECAP + m0 + rr)) * 1024 + n0;
#pragma unroll
            for (int cb = 0; cb < 8; cb++) {
                uint32_t regs[32];
                asm volatile("tcgen05.ld.sync.aligned.32x32b.x32.b32 "
                    "{%0,%1,%2,%3,%4,%5,%6,%7,%8,%9,%10,%11,%12,%13,%14,%15,"
                    "%16,%17,%18,%19,%20,%21,%22,%23,%24,%25,%26,%27,%28,%29,%30,%31}, [%32];"
                    : "=r"(regs[0]),"=r"(regs[1]),"=r"(regs[2]),"=r"(regs[3]),
                      "=r"(regs[4]),"=r"(regs[5]),"=r"(regs[6]),"=r"(regs[7]),
                      "=r"(regs[8]),"=r"(regs[9]),"=r"(regs[10]),"=r"(regs[11]),
                      "=r"(regs[12]),"=r"(regs[13]),"=r"(regs[14]),"=r"(regs[15]),
                      "=r"(regs[16]),"=r"(regs[17]),"=r"(regs[18]),"=r"(regs[19]),
                      "=r"(regs[20]),"=r"(regs[21]),"=r"(regs[22]),"=r"(regs[23]),
                      "=r"(regs[24]),"=r"(regs[25]),"=r"(regs[26]),"=r"(regs[27]),
                      "=r"(regs[28]),"=r"(regs[29]),"=r"(regs[30]),"=r"(regs[31])
                    : "r"(tbase + cb * 32));
                asm volatile("tcgen05.wait::ld.sync.aligned;" ::: "memory");
                if (val) {
                    if (STAGE == 1) {
#pragma unroll
                        for (int q = 0; q < 4; q++) {
                            uint4 w;
                            w.x = pack2(__uint_as_float(regs[q*8+0]), __uint_as_float(regs[q*8+1]));
                            w.y = pack2(__uint_as_float(regs[q*8+2]), __uint_as_float(regs[q*8+3]));
                            w.z = pack2(__uint_as_float(regs[q*8+4]), __uint_as_float(regs[q*8+5]));
                            w.w = pack2(__uint_as_float(regs[q*8+6]), __uint_as_float(regs[q*8+7]));
                            *(uint4*)(hrow + cb * 32 + q * 8) = w;
                        }
                    } else {
#pragma unroll
                        for (int q = 0; q < 8; q++) {
                            float v0 = __uint_as_float(regs[q * 4 + 0]) * gate;
                            float v1 = __uint_as_float(regs[q * 4 + 1]) * gate;
                            float v2 = __uint_as_float(regs[q * 4 + 2]) * gate;
                            float v3 = __uint_as_float(regs[q * 4 + 3]) * gate;
                            asm volatile("red.global.add.v4.f32 [%0], {%1, %2, %3, %4};"
                                :: "l"(orow + cb * 32 + q * 4),
                                   "f"(v0), "f"(v1), "f"(v2), "f"(v3) : "memory");
                        }
                    }
                }
            }
        }
    }

    __syncthreads();
    if (wid == 5) {
        asm volatile("tcgen05.relinquish_alloc_permit.cta_group::1.sync.aligned;");
        asm volatile("tcgen05.dealloc.cta_group::1.sync.aligned.b32 %0, %1;" :: "r"(tmem), "r"(512u));
    }
#endif
}

// ===========================================================================
// Fallback fp16 mma.sync GEMM (skipped when tcgen05 path ran).
template <int STAGE>
__global__ __launch_bounds__(256, 1)
void moe_fb_gemm(float* __restrict__ out) {
    if (g_tc_done) return;
    const int e = blockIdx.z;
    const int cnt = g_counts[e];
    const int m0 = blockIdx.y * 128;
    if (m0 >= cnt) return;
    const int n0 = blockIdx.x * 256;

    const __half* Asrc = ((STAGE == 1) ? g_xs : g_hs) + (size_t)e * ECAP * 1024;
    const __half* B = g_wt16 + (size_t)((STAGE == 1 ? 0 : 8) + e) * 1024 * 1024;
    const int* lst = g_lists + e * CAP + m0;

    __shared__ uint32_t sA32[128 * 20];
    __shared__ uint32_t sB32[256 * 20];

    const int tid = threadIdx.x;
    const int arow = tid >> 3, aseg = tid & 7;
    const __half* aptr[4];
#pragma unroll
    for (int p = 0; p < 4; p++) {
        int r = arow + 32 * p;
        aptr[p] = (m0 + r < cnt) ? Asrc + (size_t)(m0 + r) * 1024 + aseg * 4 : nullptr;
    }
    const int brow = tid >> 2, bseg = tid & 3;
    const __half* brp[4];
#pragma unroll
    for (int p = 0; p < 4; p++)
        brp[p] = B + (size_t)(n0 + brow + 64 * p) * 1024 + bseg * 8;

    const int warp = tid >> 5, lane = tid & 31;
    const int wm = warp & 1, wn = warp >> 1;
    const int g = lane >> 2, tg = lane & 3;

    float c[4][8][4];
#pragma unroll
    for (int i = 0; i < 4; i++)
#pragma unroll
        for (int j = 0; j < 8; j++)
#pragma unroll
            for (int q = 0; q < 4; q++) c[i][j][q] = 0.f;

    uint2 aReg[4];
    uint4 bReg[4];
#pragma unroll
    for (int p = 0; p < 4; p++)
        aReg[p] = aptr[p] ? *(const uint2*)(aptr[p]) : make_uint2(0, 0);
#pragma unroll
    for (int p = 0; p < 4; p++)
        bReg[p] = *(const uint4*)(brp[p]);

    for (int kt = 0; kt < 32; kt++) {
        if (kt) __syncthreads();
#pragma unroll
        for (int p = 0; p < 4; p++)
            *(uint2*)&sA32[(arow + 32 * p) * 20 + 2 * aseg] = aReg[p];
#pragma unroll
        for (int p = 0; p < 4; p++)
            *(uint4*)&sB32[(brow + 64 * p) * 20 + 4 * bseg] = bReg[p];
        __syncthreads();

        if (kt < 31) {
            int ko = (kt + 1) * 32;
#pragma unroll
            for (int p = 0; p < 4; p++)
                aReg[p] = aptr[p] ? *(const uint2*)(aptr[p] + ko) : make_uint2(0, 0);
#pragma unroll
            for (int p = 0; p < 4; p++)
                bReg[p] = *(const uint4*)(brp[p] + ko);
        }

#pragma unroll
        for (int ks = 0; ks < 2; ks++) {
            const int kp = 8 * ks;
            uint32_t a[4][4], b[8][2];
#pragma unroll
            for (int mf = 0; mf < 4; mf++) {
                int row = wm * 64 + mf * 16 + g;
                a[mf][0] = sA32[row * 20 + kp + tg];
                a[mf][1] = sA32[(row + 8) * 20 + kp + tg];
                a[mf][2] = sA32[row * 20 + kp + tg + 4];
                a[mf][3] = sA32[(row + 8) * 20 + kp + tg + 4];
            }
#pragma unroll
            for (int nf = 0; nf < 8; nf++) {
                int n = wn * 64 + nf * 8 + g;
                b[nf][0] = sB32[n * 20 + kp + tg];
                b[nf][1] = sB32[n * 20 + kp + tg + 4];
            }
#pragma unroll
            for (int mf = 0; mf < 4; mf++)
#pragma unroll
                for (int nf = 0; nf < 8; nf++)
                    mma_f16(c[mf][nf], a[mf], b[nf]);
        }
    }

#pragma unroll
    for (int mf = 0; mf < 4; mf++) {
#pragma unroll
        for (int half = 0; half < 2; half++) {
            int r = wm * 64 + mf * 16 + g + half * 8;
            if (m0 + r >= cnt) continue;
            if (STAGE == 1) {
                __half* hrow = g_hs + ((size_t)(e * ECAP + m0 + r)) * 1024 + n0;
#pragma unroll
                for (int nf = 0; nf < 8; nf++) {
                    int cc = wn * 64 + nf * 8 + tg * 2;
                    *(uint32_t*)(hrow + cc) =
                        pack2(c[mf][nf][half * 2 + 0], c[mf][nf][half * 2 + 1]);
                }
            } else {
                int slot = lst[r];
                float gate = g_gates[slot];
                float* orow = out + (size_t)(slot >> 1) * 1024 + n0;
#pragma unroll
                for (int nf = 0; nf < 8; nf++) {
                    int cc = wn * 64 + nf * 8 + tg * 2;
                    atomicAdd(&orow[cc], c[mf][nf][half * 2 + 0] * gate);
                    atomicAdd(&orow[cc + 1], c[mf][nf][half * 2 + 1] * gate);
                }
            }
        }
    }
}

// ===========================================================================
typedef CUresult (*tmap_encode_fn)(
    CUtensorMap*, CUtensorMapDataType, cuuint32_t, void*,
    const cuuint64_t*, const cuuint64_t*, const cuuint32_t*, const cuuint32_t*,
    CUtensorMapInterleave, CUtensorMapSwizzle, CUtensorMapL2promotion,
    CUtensorMapFloatOOBfill);

static void encode_fp16_3d(tmap_encode_fn enc, CUtensorMap* m, void* base,
                           cuuint64_t d0, cuuint64_t d1, cuuint64_t d2,
                           cuuint32_t b0, cuuint32_t b1) {
    cuuint64_t dims[3] = {d0, d1, d2};
    cuuint64_t strides[2] = {d0 * 2, d0 * d1 * 2};
    cuuint32_t box[3] = {b0, b1, 1};
    cuuint32_t es[3] = {1, 1, 1};
    enc(m, CU_TENSOR_MAP_DATA_TYPE_FLOAT16, 3, base, dims, strides, box, es,
        CU_TENSOR_MAP_INTERLEAVE_NONE, CU_TENSOR_MAP_SWIZZLE_128B,
        CU_TENSOR_MAP_L2_PROMOTION_L2_128B, CU_TENSOR_MAP_FLOAT_OOB_FILL_NONE);
}

extern "C" void kernel_launch(void* const* d_in, const int* in_sizes, int n_in,
                              void* d_out, int out_size) {
    const float* x  = (const float*)d_in[0];
    const float* Wr = (const float*)d_in[1];
    const float* Wi = (const float*)d_in[2];
    const float* Wo = (const float*)d_in[3];
    float* out = (float*)d_out;
    (void)in_sizes; (void)n_in; (void)out_size;

    void* fnp = nullptr;
    cudaDriverEntryPointQueryResult qr;
    cudaGetDriverEntryPoint("cuTensorMapEncodeTiled", &fnp, cudaEnableDefault, &qr);
    if (fnp) {
        tmap_encode_fn enc = (tmap_encode_fn)fnp;
        void *xs_p = nullptr, *hs_p = nullptr, *wt_p = nullptr;
        cudaGetSymbolAddress(&xs_p, g_xs);
        cudaGetSymbolAddress(&hs_p, g_hs);
        cudaGetSymbolAddress(&wt_p, g_wt16);
        static CUtensorMap hA1, hA2, hB;
        encode_fp16_3d(enc, &hA1, xs_p, 1024, ECAP, NEXP, KC, TM);
        encode_fp16_3d(enc, &hA2, hs_p, 1024, ECAP, NEXP, KC, TM);
        encode_fp16_3d(enc, &hB,  wt_p, 1024, 1024, 16,  KC, TN);
        cudaMemcpyToSymbolAsync(g_tmA1, &hA1, sizeof(CUtensorMap), 0, cudaMemcpyHostToDevice, 0);
        cudaMemcpyToSymbolAsync(g_tmA2, &hA2, sizeof(CUtensorMap), 0, cudaMemcpyHostToDevice, 0);
        cudaMemcpyToSymbolAsync(g_tmB,  &hB,  sizeof(CUtensorMap), 0, cudaMemcpyHostToDevice, 0);
    }

    cudaFuncSetAttribute(moe_tc_gemm<1>, cudaFuncAttributeMaxDynamicSharedMemorySize, SMEM_TOTAL);
    cudaFuncSetAttribute(moe_tc_gemm<2>, cudaFuncAttributeMaxDynamicSharedMemorySize, SMEM_TOTAL);

    // All work on the default stream — known-good graph-capture structure (R5).
    init_kernel<<<1, 32>>>();
    cudaMemsetAsync(d_out, 0, (size_t)T_TOK * 1024 * sizeof(float), 0);
    router_kernel<<<T_TOK / 8, 256>>>(x, Wr);
    transpose_half_kernel<<<dim3(32, 32, 16), dim3(32, 8)>>>(Wi, Wo);
    gather_x_kernel<<<dim3(ECAP / 8, NEXP), 256>>>(x);

    dim3 gtc(1024 / TN, ECAP / TM, NEXP);
    dim3 gfb(1024 / 256, ECAP / 128, NEXP);
    moe_tc_gemm<1><<<gtc, 192, SMEM_TOTAL>>>(out);
    moe_fb_gemm<1><<<gfb, 256>>>(out);
    moe_tc_gemm<2><<<gtc, 192, SMEM_TOTAL>>>(out);
    moe_fb_gemm<2><<<gfb, 256>>>(out);
}

// round 8
// speedup vs baseline: 3.0974x; 1.0092x over previous
#include <cuda_runtime.h>
#include <cuda.h>
#include <cuda_fp16.h>
#include <cstdint>

// ===========================================================================
#if defined(__CUDA_ARCH_FEAT_SM100_ALL) || defined(__CUDA_ARCH_FEAT_SM103_ALL)
#define HAS_TC 1
#else
#define HAS_TC 0
#endif

#define T_TOK 8192
#define NEXP  8
#define NSLOT (T_TOK*2)
#define CAP   NSLOT
#define ECAP  8192

// tcgen05 tiling: fp16, chunk = 64 halves = 128B row; TM=256 via 2 MMAs
#define NST   3
#define KC    64
#define NCHUNK 16
#define TM    256
#define TN    256
#define A_TILE_B (TM*128)    // 32 KB
#define B_TILE_B (TN*128)    // 32 KB
#define SM_TMEM  0
#define SM_FULL  64
#define SM_EMPTY 128
#define SM_DONE  192
#define SM_A     1024
#define SM_B     (SM_A + NST*A_TILE_B)
#define SMEM_TOTAL (SM_B + NST*B_TILE_B)   // 197632

#define IDESC ((1u<<4)|((unsigned)(TN/8)<<17)|((unsigned)(128/16)<<24))

// ===========================================================================
__device__ __half g_xs[(size_t)NEXP * ECAP * 1024];
__device__ __half g_hs[(size_t)NEXP * ECAP * 1024];
__device__ __half g_wt16[(size_t)16 * 1024 * 1024];
__device__ float  g_gates[NSLOT];
__device__ int    g_lists[NEXP * CAP];
__device__ int    g_counts[NEXP];
__device__ int    g_tc_done;
__device__ __align__(128) CUtensorMap g_tmA1;
__device__ __align__(128) CUtensorMap g_tmA2;
__device__ __align__(128) CUtensorMap g_tmB;

// ===========================================================================
__device__ __forceinline__ uint32_t smem_u32(const void* p) {
    uint32_t a;
    asm("{ .reg .u64 t; cvta.to.shared.u64 t, %1; cvt.u32.u64 %0, t; }" : "=r"(a) : "l"(p));
    return a;
}
__device__ __forceinline__ uint32_t elect_one_pred() {
    uint32_t p;
    asm volatile("{\n\t.reg .pred p;\n\telect.sync _|p, 0xFFFFFFFF;\n\t"
                 "selp.b32 %0, 1, 0, p;\n\t}" : "=r"(p));
    return p;
}
#define MBARRIER_INIT(addr, cnt) \
    asm volatile("mbarrier.init.shared.b64 [%0], %1;" :: "r"((uint32_t)(addr)), "r"((uint32_t)(cnt)) : "memory")
#define MBARRIER_EXPECT_TX(addr, tx) \
    asm volatile("mbarrier.arrive.expect_tx.shared.b64 _, [%0], %1;" :: "r"((uint32_t)(addr)), "r"((uint32_t)(tx)) : "memory")
#define MBARRIER_WAIT_PARITY(addr, parity) do { \
    uint32_t _m = (uint32_t)(addr); uint32_t _p = (uint32_t)(parity); uint32_t _d; \
    asm volatile("{\n\t.reg .pred p;\n\t" \
        "mbarrier.try_wait.parity.acquire.cta.shared::cta.b64 p, [%1], %2;\n\t" \
        "selp.b32 %0, 1, 0, p;\n\t}" : "=r"(_d) : "r"(_m), "r"(_p) : "memory"); \
    if (!_d) { \
        asm volatile("{\n\t.reg .pred P1;\n\t" \
            "WL_%=:\n\t" \
            "mbarrier.try_wait.parity.acquire.cta.shared::cta.b64 P1, [%0], %1, 0x989680;\n\t" \
            "@P1 bra.uni WD_%=;\n\t" \
            "bra.uni WL_%=;\n\t" \
            "WD_%=:\n\t}" :: "r"(_m), "r"(_p) : "memory"); \
    } \
} while (0)

__device__ __forceinline__ uint32_t pack2(float a, float b) {
    __half2 h = __floats2half2_rn(a, b);
    return *reinterpret_cast<uint32_t*>(&h);
}
__device__ __forceinline__ void mma_f16(float* c, const uint32_t* a, const uint32_t* b) {
    asm volatile(
        "mma.sync.aligned.m16n8k16.row.col.f32.f16.f16.f32 "
        "{%0,%1,%2,%3}, {%4,%5,%6,%7}, {%8,%9}, {%0,%1,%2,%3};\n"
        : "+f"(c[0]), "+f"(c[1]), "+f"(c[2]), "+f"(c[3])
        : "r"(a[0]), "r"(a[1]), "r"(a[2]), "r"(a[3]), "r"(b[0]), "r"(b[1]));
}

static constexpr uint64_t SMEM_DESC_BASE_SW128 =
    (uint64_t(2) << 61) | (uint64_t(1) << 46) | (uint64_t(64) << 32) | (uint64_t(1) << 16);
#define MAKE_SMEM_DESC(a) (SMEM_DESC_BASE_SW128 | ((uint64_t)((a) >> 4) & 0x3FFF))

// ===========================================================================
__global__ void init_kernel() {
    if (threadIdx.x < NEXP) g_counts[threadIdx.x] = 0;
#if HAS_TC
    if (threadIdx.x == 0) g_tc_done = 1;
#else
    if (threadIdx.x == 0) g_tc_done = 0;
#endif
}

// Router (validated R1)
__global__ void router_kernel(const float* __restrict__ x,
                              const float* __restrict__ Wr) {
    __shared__ float sWr[NEXP][1024];
    int tid = threadIdx.x;
    for (int i = tid; i < 1024 * NEXP; i += blockDim.x) {
        int d = i >> 3, e = i & 7;
        sWr[e][d] = Wr[i];
    }
    __syncthreads();
    int warp = tid >> 5, lane = tid & 31;
    int token = blockIdx.x * 8 + warp;
    if (token >= T_TOK) return;
    const float* xr = x + (size_t)token * 1024;
    float acc[NEXP];
#pragma unroll
    for (int e = 0; e < NEXP; e++) acc[e] = 0.f;
    for (int i = lane; i < 1024; i += 32) {
        float xv = xr[i];
#pragma unroll
        for (int e = 0; e < NEXP; e++) acc[e] += xv * sWr[e][i];
    }
#pragma unroll
    for (int e = 0; e < NEXP; e++)
#pragma unroll
        for (int off = 16; off > 0; off >>= 1)
            acc[e] += __shfl_xor_sync(0xffffffffu, acc[e], off);
    if (lane == 0) {
        float mx = acc[0];
#pragma unroll
        for (int e = 1; e < NEXP; e++) mx = fmaxf(mx, acc[e]);
        float p[NEXP], s = 0.f;
#pragma unroll
        for (int e = 0; e < NEXP; e++) { p[e] = expf(acc[e] - mx); s += p[e]; }
        float inv = 1.f / s;
#pragma unroll
        for (int e = 0; e < NEXP; e++) p[e] *= inv;
        int i0 = 0; float b0 = p[0];
#pragma unroll
        for (int e = 1; e < NEXP; e++) if (p[e] > b0) { b0 = p[e]; i0 = e; }
        int i1 = -1; float b1 = -1.f;
#pragma unroll
        for (int e = 0; e < NEXP; e++)
            if (e != i0 && p[e] > b1) { b1 = p[e]; i1 = e; }
        int s0 = token * 2, s1 = token * 2 + 1;
        g_gates[s0] = b0;
        g_gates[s1] = b1;
        int pos0 = atomicAdd(&g_counts[i0], 1);
        g_lists[i0 * CAP + pos0] = s0;
        int pos1 = atomicAdd(&g_counts[i1], 1);
        g_lists[i1 * CAP + pos1] = s1;
    }
}

// Weights: [e][k][n] fp32 -> [mat*8+e][n][k] fp16
__global__ void transpose_half_kernel(const float* __restrict__ Wi,
                                      const float* __restrict__ Wo) {
    __shared__ float t[32][33];
    int mat = blockIdx.z >> 3, e = blockIdx.z & 7;
    const float* src = (mat ? Wo : Wi) + (size_t)e * 1024 * 1024;
    __half* dst = g_wt16 + (size_t)blockIdx.z * 1024 * 1024;
    int k0 = blockIdx.y * 32, n0 = blockIdx.x * 32;
    int tx = threadIdx.x, ty = threadIdx.y;
#pragma unroll
    for (int i = 0; i < 4; i++)
        t[ty + 8 * i][tx] = src[(size_t)(k0 + ty + 8 * i) * 1024 + n0 + tx];
    __syncthreads();
#pragma unroll
    for (int i = 0; i < 4; i++) {
        int n = ty + 8 * i;
        dst[(size_t)(n0 + n) * 1024 + k0 + tx] = __float2half_rn(t[tx][n]);
    }
}

// Coalesced gather: block handles 8 rows; 256 threads cooperate per row.
// Thread t reads float4 #t of the row (warp = 512B contiguous read),
// writes half2x2 (warp = 256B contiguous write).
__global__ __launch_bounds__(256)
void gather_x_kernel(const float* __restrict__ x) {
    int e = blockIdx.y;
    int cnt = g_counts[e];
    int row0 = blockIdx.x * 8;
    if (row0 >= cnt) return;
    int t = threadIdx.x;
    int nrows = min(8, cnt - row0);
    for (int r = 0; r < nrows; r++) {
        int token = g_lists[e * CAP + row0 + r] >> 1;
        const float4* src = (const float4*)(x + (size_t)token * 1024);
        uint2* dst = (uint2*)(g_xs + ((size_t)(e * ECAP + row0 + r)) * 1024);
        float4 v = src[t];
        uint2 w;
        w.x = pack2(v.x, v.y);
        w.y = pack2(v.z, v.w);
        dst[t] = w;
    }
}

// ===========================================================================
// Pure-TMA tcgen05 fp16 grouped GEMM, TM=256 (two M=128 MMAs, full TMEM).
// STAGE 1: A=g_xs -> g_hs fp16.  STAGE 2: A=g_hs -> red.add into out.
template <int STAGE>
__global__ __launch_bounds__(192, 1)
void moe_tc_gemm(float* __restrict__ out) {
#if HAS_TC
    extern __shared__ char smem[];
    const int e = blockIdx.z;
    const int cnt = g_counts[e];
    const int m0 = blockIdx.y * TM;
    if (m0 >= cnt) return;
    const int n0 = blockIdx.x * TN;
    const uint32_t sb = smem_u32(smem);
    const int tid = threadIdx.x, wid = tid >> 5;

    if (tid == 0) {
#pragma unroll
        for (int s = 0; s < NST; s++) {
            MBARRIER_INIT(sb + SM_FULL + 8 * s, 1);
            MBARRIER_INIT(sb + SM_EMPTY + 8 * s, 1);
        }
        MBARRIER_INIT(sb + SM_DONE, 1);
    }
    if (wid == 5)
        asm volatile("tcgen05.alloc.cta_group::1.sync.aligned.shared::cta.b32 [%0], %1;"
                     :: "r"(sb + SM_TMEM), "r"(512u) : "memory");
    __syncthreads();
    uint32_t tmem;
    asm volatile("ld.shared.b32 %0, [%1];" : "=r"(tmem) : "r"(sb + SM_TMEM));

    if (wid == 4) {
        if (elect_one_pred()) {
            const CUtensorMap* tmA = (STAGE == 1) ? &g_tmA1 : &g_tmA2;
            const CUtensorMap* tmB = &g_tmB;
            int zb = (STAGE == 1) ? e : NEXP + e;
            int s = 0, ph = 1;
            for (int c = 0; c < NCHUNK; c++) {
                MBARRIER_WAIT_PARITY(sb + SM_EMPTY + 8 * s, ph);
                MBARRIER_EXPECT_TX(sb + SM_FULL + 8 * s, A_TILE_B + B_TILE_B);
                asm volatile("cp.async.bulk.tensor.3d.shared::cta.global.tile.mbarrier::complete_tx::bytes "
                    "[%0], [%1, {%2, %3, %4}], [%5];"
                    :: "r"(sb + SM_A + s * A_TILE_B), "l"(tmA),
                       "r"(c * KC), "r"(m0), "r"(e),
                       "r"(sb + SM_FULL + 8 * s) : "memory");
                asm volatile("cp.async.bulk.tensor.3d.shared::cta.global.tile.mbarrier::complete_tx::bytes "
                    "[%0], [%1, {%2, %3, %4}], [%5];"
                    :: "r"(sb + SM_B + s * B_TILE_B), "l"(tmB),
                       "r"(c * KC), "r"(n0), "r"(zb),
                       "r"(sb + SM_FULL + 8 * s) : "memory");
                if (++s == NST) { s = 0; ph ^= 1; }
            }
        }
    } else if (wid == 5) {
        if (elect_one_pred()) {
            int s = 0, ph = 0;
            for (int c = 0; c < NCHUNK; c++) {
                MBARRIER_WAIT_PARITY(sb + SM_FULL + 8 * s, ph);
                uint64_t ad0 = MAKE_SMEM_DESC(sb + SM_A + s * A_TILE_B);
                uint64_t ad1 = MAKE_SMEM_DESC(sb + SM_A + s * A_TILE_B + A_TILE_B / 2);
                uint64_t bd  = MAKE_SMEM_DESC(sb + SM_B + s * B_TILE_B);
#pragma unroll
                for (int sub = 0; sub < 4; sub++) {
                    uint32_t en = (unsigned)((c | sub) != 0);
                    asm volatile("{\n\t.reg .pred p;\n\tsetp.ne.u32 p, %6, 0;\n\t"
                        "tcgen05.mma.cta_group::1.kind::f16 [%0], %1, %2, %3, "
                        "{%4, %4, %4, %4}, p;\n\t}"
                        :: "r"(tmem), "l"(ad0 + 2 * sub), "l"(bd + 2 * sub),
                           "r"(IDESC), "r"(0u), "r"(0u), "r"(en) : "memory");
                    asm volatile("{\n\t.reg .pred p;\n\tsetp.ne.u32 p, %6, 0;\n\t"
                        "tcgen05.mma.cta_group::1.kind::f16 [%0], %1, %2, %3, "
                        "{%4, %4, %4, %4}, p;\n\t}"
                        :: "r"(tmem + 256), "l"(ad1 + 2 * sub), "l"(bd + 2 * sub),
                           "r"(IDESC), "r"(0u), "r"(0u), "r"(en) : "memory");
                }
                asm volatile("tcgen05.commit.cta_group::1.mbarrier::arrive::one.shared::cluster.b64 [%0];"
                             :: "r"(sb + SM_EMPTY + 8 * s) : "memory");
                if (++s == NST) { s = 0; ph ^= 1; }
            }
            asm volatile("tcgen05.commit.cta_group::1.mbarrier::arrive::one.shared::cluster.b64 [%0];"
                         :: "r"(sb + SM_DONE) : "memory");
        }
    }

    if (wid < 4) {
        MBARRIER_WAIT_PARITY(sb + SM_DONE, 0);
        asm volatile("tcgen05.fence::after_thread_sync;" ::: "memory");
        const int* lst = g_lists + e * CAP + m0;
#pragma unroll
        for (int half = 0; half < 2; half++) {
            int rr = half * 128 + tid;
            bool val = (m0 + rr) < cnt;
            uint32_t tbase = tmem + half * 256;
            int slot = (STAGE == 2 && val) ? lst[rr] : 0;
            float gate = (STAGE == 2) ? (val ? g_gates[slot] : 0.f) : 1.f;
            float* orow = out + (size_t)(slot >> 1) * 1024 + n0;
            __half* hrow = g_hs + ((size_t)(e * ECAP + m0 + rr)) * 1024 + n0;
#pragma unroll
            for (int cb = 0; cb < 8; cb++) {
                uint32_t regs[32];
                asm volatile("tcgen05.ld.sync.aligned.32x32b.x32.b32 "
                    "{%0,%1,%2,%3,%4,%5,%6,%7,%8,%9,%10,%11,%12,%13,%14,%15,"
                    "%16,%17,%18,%19,%20,%21,%22,%23,%24,%25,%26,%27,%28,%29,%30,%31}, [%32];"
                    : "=r"(regs[0]),"=r"(regs[1]),"=r"(regs[2]),"=r"(regs[3]),
                      "=r"(regs[4]),"=r"(regs[5]),"=r"(regs[6]),"=r"(regs[7]),
                      "=r"(regs[8]),"=r"(regs[9]),"=r"(regs[10]),"=r"(regs[11]),
                      "=r"(regs[12]),"=r"(regs[13]),"=r"(regs[14]),"=r"(regs[15]),
                      "=r"(regs[16]),"=r"(regs[17]),"=r"(regs[18]),"=r"(regs[19]),
                      "=r"(regs[20]),"=r"(regs[21]),"=r"(regs[22]),"=r"(regs[23]),
                      "=r"(regs[24]),"=r"(regs[25]),"=r"(regs[26]),"=r"(regs[27]),
                      "=r"(regs[28]),"=r"(regs[29]),"=r"(regs[30]),"=r"(regs[31])
                    : "r"(tbase + cb * 32));
                asm volatile("tcgen05.wait::ld.sync.aligned;" ::: "memory");
                if (val) {
                    if (STAGE == 1) {
#pragma unroll
                        for (int q = 0; q < 4; q++) {
                            uint4 w;
                            w.x = pack2(__uint_as_float(regs[q*8+0]), __uint_as_float(regs[q*8+1]));
                            w.y = pack2(__uint_as_float(regs[q*8+2]), __uint_as_float(regs[q*8+3]));
                            w.z = pack2(__uint_as_float(regs[q*8+4]), __uint_as_float(regs[q*8+5]));
                            w.w = pack2(__uint_as_float(regs[q*8+6]), __uint_as_float(regs[q*8+7]));
                            *(uint4*)(hrow + cb * 32 + q * 8) = w;
                        }
                    } else {
#pragma unroll
                        for (int q = 0; q < 8; q++) {
                            float v0 = __uint_as_float(regs[q * 4 + 0]) * gate;
                            float v1 = __uint_as_float(regs[q * 4 + 1]) * gate;
                            float v2 = __uint_as_float(regs[q * 4 + 2]) * gate;
                            float v3 = __uint_as_float(regs[q * 4 + 3]) * gate;
                            asm volatile("red.global.add.v4.f32 [%0], {%1, %2, %3, %4};"
                                :: "l"(orow + cb * 32 + q * 4),
                                   "f"(v0), "f"(v1), "f"(v2), "f"(v3) : "memory");
                        }
                    }
                }
            }
        }
    }

    __syncthreads();
    if (wid == 5) {
        asm volatile("tcgen05.relinquish_alloc_permit.cta_group::1.sync.aligned;");
        asm volatile("tcgen05.dealloc.cta_group::1.sync.aligned.b32 %0, %1;" :: "r"(tmem), "r"(512u));
    }
#endif
}

// ===========================================================================
// Fallback fp16 mma.sync GEMM (skipped when tcgen05 path ran).
template <int STAGE>
__global__ __launch_bounds__(256, 1)
void moe_fb_gemm(float* __restrict__ out) {
    if (g_tc_done) return;
    const int e = blockIdx.z;
    const int cnt = g_counts[e];
    const int m0 = blockIdx.y * 128;
    if (m0 >= cnt) return;
    const int n0 = blockIdx.x * 256;

    const __half* Asrc = ((STAGE == 1) ? g_xs : g_hs) + (size_t)e * ECAP * 1024;
    const __half* B = g_wt16 + (size_t)((STAGE == 1 ? 0 : 8) + e) * 1024 * 1024;
    const int* lst = g_lists + e * CAP + m0;

    __shared__ uint32_t sA32[128 * 20];
    __shared__ uint32_t sB32[256 * 20];

    const int tid = threadIdx.x;
    const int arow = tid >> 3, aseg = tid & 7;
    const __half* aptr[4];
#pragma unroll
    for (int p = 0; p < 4; p++) {
        int r = arow + 32 * p;
        aptr[p] = (m0 + r < cnt) ? Asrc + (size_t)(m0 + r) * 1024 + aseg * 4 : nullptr;
    }
    const int brow = tid >> 2, bseg = tid & 3;
    const __half* brp[4];
#pragma unroll
    for (int p = 0; p < 4; p++)
        brp[p] = B + (size_t)(n0 + brow + 64 * p) * 1024 + bseg * 8;

    const int warp = tid >> 5, lane = tid & 31;
    const int wm = warp & 1, wn = warp >> 1;
    const int g = lane >> 2, tg = lane & 3;

    float c[4][8][4];
#pragma unroll
    for (int i = 0; i < 4; i++)
#pragma unroll
        for (int j = 0; j < 8; j++)
#pragma unroll
            for (int q = 0; q < 4; q++) c[i][j][q] = 0.f;

    uint2 aReg[4];
    uint4 bReg[4];
#pragma unroll
    for (int p = 0; p < 4; p++)
        aReg[p] = aptr[p] ? *(const uint2*)(aptr[p]) : make_uint2(0, 0);
#pragma unroll
    for (int p = 0; p < 4; p++)
        bReg[p] = *(const uint4*)(brp[p]);

    for (int kt = 0; kt < 32; kt++) {
        if (kt) __syncthreads();
#pragma unroll
        for (int p = 0; p < 4; p++)
            *(uint2*)&sA32[(arow + 32 * p) * 20 + 2 * aseg] = aReg[p];
#pragma unroll
        for (int p = 0; p < 4; p++)
            *(uint4*)&sB32[(brow + 64 * p) * 20 + 4 * bseg] = bReg[p];
        __syncthreads();

        if (kt < 31) {
            int ko = (kt + 1) * 32;
#pragma unroll
            for (int p = 0; p < 4; p++)
                aReg[p] = aptr[p] ? *(const uint2*)(aptr[p] + ko) : make_uint2(0, 0);
#pragma unroll
            for (int p = 0; p < 4; p++)
                bReg[p] = *(const uint4*)(brp[p] + ko);
        }

#pragma unroll
        for (int ks = 0; ks < 2; ks++) {
            const int kp = 8 * ks;
            uint32_t a[4][4], b[8][2];
#pragma unroll
            for (int mf = 0; mf < 4; mf++) {
                int row = wm * 64 + mf * 16 + g;
                a[mf][0] = sA32[row * 20 + kp + tg];
                a[mf][1] = sA32[(row + 8) * 20 + kp + tg];
                a[mf][2] = sA32[row * 20 + kp + tg + 4];
                a[mf][3] = sA32[(row + 8) * 20 + kp + tg + 4];
            }
#pragma unroll
            for (int nf = 0; nf < 8; nf++) {
                int n = wn * 64 + nf * 8 + g;
                b[nf][0] = sB32[n * 20 + kp + tg];
                b[nf][1] = sB32[n * 20 + kp + tg + 4];
            }
#pragma unroll
            for (int mf = 0; mf < 4; mf++)
#pragma unroll
                for (int nf = 0; nf < 8; nf++)
                    mma_f16(c[mf][nf], a[mf], b[nf]);
        }
    }

#pragma unroll
    for (int mf = 0; mf < 4; mf++) {
#pragma unroll
        for (int half = 0; half < 2; half++) {
            int r = wm * 64 + mf * 16 + g + half * 8;
            if (m0 + r >= cnt) continue;
            if (STAGE == 1) {
                __half* hrow = g_hs + ((size_t)(e * ECAP + m0 + r)) * 1024 + n0;
#pragma unroll
                for (int nf = 0; nf < 8; nf++) {
                    int cc = wn * 64 + nf * 8 + tg * 2;
                    *(uint32_t*)(hrow + cc) =
                        pack2(c[mf][nf][half * 2 + 0], c[mf][nf][half * 2 + 1]);
                }
            } else {
                int slot = lst[r];
                float gate = g_gates[slot];
                float* orow = out + (size_t)(slot >> 1) * 1024 + n0;
#pragma unroll
                for (int nf = 0; nf < 8; nf++) {
                    int cc = wn * 64 + nf * 8 + tg * 2;
                    atomicAdd(&orow[cc], c[mf][nf][half * 2 + 0] * gate);
                    atomicAdd(&orow[cc + 1], c[mf][nf][half * 2 + 1] * gate);
                }
            }
        }
    }
}

// ===========================================================================
typedef CUresult (*tmap_encode_fn)(
    CUtensorMap*, CUtensorMapDataType, cuuint32_t, void*,
    const cuuint64_t*, const cuuint64_t*, const cuuint32_t*, const cuuint32_t*,
    CUtensorMapInterleave, CUtensorMapSwizzle, CUtensorMapL2promotion,
    CUtensorMapFloatOOBfill);

static void encode_fp16_3d(tmap_encode_fn enc, CUtensorMap* m, void* base,
                           cuuint64_t d0, cuuint64_t d1, cuuint64_t d2,
                           cuuint32_t b0, cuuint32_t b1) {
    cuuint64_t dims[3] = {d0, d1, d2};
    cuuint64_t strides[2] = {d0 * 2, d0 * d1 * 2};
    cuuint32_t box[3] = {b0, b1, 1};
    cuuint32_t es[3] = {1, 1, 1};
    enc(m, CU_TENSOR_MAP_DATA_TYPE_FLOAT16, 3, base, dims, strides, box, es,
        CU_TENSOR_MAP_INTERLEAVE_NONE, CU_TENSOR_MAP_SWIZZLE_128B,
        CU_TENSOR_MAP_L2_PROMOTION_L2_128B, CU_TENSOR_MAP_FLOAT_OOB_FILL_NONE);
}

extern "C" void kernel_launch(void* const* d_in, const int* in_sizes, int n_in,
                              void* d_out, int out_size) {
    const float* x  = (const float*)d_in[0];
    const float* Wr = (const float*)d_in[1];
    const float* Wi = (const float*)d_in[2];
    const float* Wo = (const float*)d_in[3];
    float* out = (float*)d_out;
    (void)in_sizes; (void)n_in; (void)out_size;

    void* fnp = nullptr;
    cudaDriverEntryPointQueryResult qr;
    cudaGetDriverEntryPoint("cuTensorMapEncodeTiled", &fnp, cudaEnableDefault, &qr);
    if (fnp) {
        tmap_encode_fn enc = (tmap_encode_fn)fnp;
        void *xs_p = nullptr, *hs_p = nullptr, *wt_p = nullptr;
        cudaGetSymbolAddress(&xs_p, g_xs);
        cudaGetSymbolAddress(&hs_p, g_hs);
        cudaGetSymbolAddress(&wt_p, g_wt16);
        static CUtensorMap hA1, hA2, hB;
        encode_fp16_3d(enc, &hA1, xs_p, 1024, ECAP, NEXP, KC, TM);
        encode_fp16_3d(enc, &hA2, hs_p, 1024, ECAP, NEXP, KC, TM);
        encode_fp16_3d(enc, &hB,  wt_p, 1024, 1024, 16,  KC, TN);
        cudaMemcpyToSymbolAsync(g_tmA1, &hA1, sizeof(CUtensorMap), 0, cudaMemcpyHostToDevice, 0);
        cudaMemcpyToSymbolAsync(g_tmA2, &hA2, sizeof(CUtensorMap), 0, cudaMemcpyHostToDevice, 0);
        cudaMemcpyToSymbolAsync(g_tmB,  &hB,  sizeof(CUtensorMap), 0, cudaMemcpyHostToDevice, 0);
    }

    cudaFuncSetAttribute(moe_tc_gemm<1>, cudaFuncAttributeMaxDynamicSharedMemorySize, SMEM_TOTAL);
    cudaFuncSetAttribute(moe_tc_gemm<2>, cudaFuncAttributeMaxDynamicSharedMemorySize, SMEM_TOTAL);

    // All work on the default stream — known-good graph-capture structure (R5).
    init_kernel<<<1, 32>>>();
    cudaMemsetAsync(d_out, 0, (size_t)T_TOK * 1024 * sizeof(float), 0);
    router_kernel<<<T_TOK / 8, 256>>>(x, Wr);
    transpose_half_kernel<<<dim3(32, 32, 16), dim3(32, 8)>>>(Wi, Wo);
    gather_x_kernel<<<dim3(ECAP / 8, NEXP), 256>>>(x);

    dim3 gtc(1024 / TN, ECAP / TM, NEXP);
    dim3 gfb(1024 / 256, ECAP / 128, NEXP);
    moe_tc_gemm<1><<<gtc, 192, SMEM_TOTAL>>>(out);
    moe_fb_gemm<1><<<gfb, 256>>>(out);
    moe_tc_gemm<2><<<gtc, 192, SMEM_TOTAL>>>(out);
    moe_fb_gemm<2><<<gfb, 256>>>(out);
}